// round 6
// baseline (speedup 1.0000x reference)
#include <cuda_runtime.h>

// Problem constants (fixed by the reference)
#define NN 1024   // grid size (rows of x)
#define MM 256    // measurements
#define BB 512    // batch (cols of x)
#define LL 10     // layers
#define BETA 0.01f

#define BK 32     // k-chunk
#define BR 64     // rows per block
#define BC 64     // cols per block
// 256 threads = 16(ty) x 16(tx); micro-tile: 2 row-pairs (4 rows) x 4 cols.

typedef unsigned long long u64;

__device__ __forceinline__ u64 pk(float lo, float hi) {
    u64 r; asm("mov.b64 %0, {%1, %2};" : "=l"(r) : "f"(lo), "f"(hi)); return r;
}
__device__ __forceinline__ void upk(float& lo, float& hi, u64 v) {
    asm("mov.b64 {%0, %1}, %2;" : "=f"(lo), "=f"(hi) : "l"(v));
}
__device__ __forceinline__ void fma2(u64& d, u64 a, u64 b) {
    asm("fma.rn.f32x2 %0, %1, %2, %0;" : "+l"(d) : "l"(a), "l"(b));
}

// Ping-pong x buffers (no cudaMalloc allowed)
__device__ float2 g_bufA[NN * BB];
__device__ float2 g_bufB[NN * BB];

#define SA_STRIDE 66   // [BK][66] padded: even stride keeps float2 alignment, kills STS 32-way conflicts

__global__ __launch_bounds__(256, 2)
void lista_layer(const float* __restrict__ v_re, const float* __restrict__ v_im,
                 const float* __restrict__ W2_re, const float* __restrict__ W2_im,
                 const float* __restrict__ y_re,  const float* __restrict__ y_im,
                 int l)
{
    // uBuf is a union:
    //   phase 1: sAre = uBuf[0 .. 2111]   ([BK][66] W2 re, row-pair consumable)
    //            sAim = uBuf[2112 .. 4223]
    //   phase 2: v1re = uBuf[0 .. 2047], v1im = uBuf[2112 .. 4159]
    __shared__ __align__(8) float uBuf[4224];
    __shared__ float sBre[BK][BC];
    __shared__ float sBim[BK][BC];

    float* sAre = uBuf;
    float* sAim = uBuf + 2112;
    float* v1re = uBuf;
    float* v1im = uBuf + 2112;

    const float2* xin  = (l & 1) ? g_bufA : g_bufB;
    float2*       xout = (l & 1) ? g_bufB : g_bufA;

    const int tid = threadIdx.x;
    const int ty  = tid >> 4;   // 0..15
    const int tx  = tid & 15;   // 0..15
    const int rowBase = blockIdx.y * BR;
    const int colBase = blockIdx.x * BC;

    // Accumulators: [pair p][col q], rows (rowBase+2ty+32p, +1), col colBase+tx+16q
    u64 accRe[2][4], accIm[2][4];
#pragma unroll
    for (int p = 0; p < 2; p++)
#pragma unroll
        for (int q = 0; q < 4; q++) { accRe[p][q] = 0ull; accIm[p][q] = 0ull; }

    // ---------------- Phase 1: W2_l @ y  (K = M = 256) ----------------
    const float* w2r = W2_re + (size_t)l * NN * MM;
    const float* w2i = W2_im + (size_t)l * NN * MM;
    for (int m0 = 0; m0 < MM; m0 += BK) {
        // A tile: planar [kk][r], LDG coalesced along m
#pragma unroll
        for (int e = tid; e < BR * BK; e += 256) {
            int r  = e >> 5;
            int kk = e & 31;
            size_t g = (size_t)(rowBase + r) * MM + (m0 + kk);
            sAre[kk * SA_STRIDE + r] = w2r[g];
            sAim[kk * SA_STRIDE + r] = w2i[g];
        }
        // B tile: planar [kk][c], LDG coalesced along b
#pragma unroll
        for (int e = tid; e < BK * BC; e += 256) {
            int kk = e >> 6;
            int c  = e & 63;
            size_t g = (size_t)(m0 + kk) * BB + (colBase + c);
            sBre[kk][c] = y_re[g];
            sBim[kk][c] = y_im[g];
        }
        __syncthreads();
#pragma unroll 4
        for (int kk = 0; kk < BK; kk++) {
            u64 BXX[4], BYY[4];
#pragma unroll
            for (int q = 0; q < 4; q++) {
                float bx = sBre[kk][tx + 16 * q];
                float by = sBim[kk][tx + 16 * q];
                BXX[q] = pk(bx, bx);
                BYY[q] = pk(by, by);
            }
            u64 AX[2], AY[2], NAY[2];
#pragma unroll
            for (int p = 0; p < 2; p++) {
                int rp = 2 * ty + 32 * p;
                float2 ar = *(const float2*)(sAre + kk * SA_STRIDE + rp);
                float2 ai = *(const float2*)(sAim + kk * SA_STRIDE + rp);
                AX[p]  = pk(ar.x, ar.y);
                AY[p]  = pk(ai.x, ai.y);
                NAY[p] = pk(-ai.x, -ai.y);
            }
#pragma unroll
            for (int p = 0; p < 2; p++)
#pragma unroll
                for (int q = 0; q < 4; q++) {
                    fma2(accRe[p][q], AX[p],  BXX[q]);
                    fma2(accRe[p][q], NAY[p], BYY[q]);
                    fma2(accIm[p][q], AX[p],  BYY[q]);
                    fma2(accIm[p][q], AY[p],  BXX[q]);
                }
        }
        __syncthreads();
    }

    // ---------------- Phase 2: Toeplitz(v_l) @ x  (K = N = 1024) ----------------
    if (l > 0) {
        // Build planar v1 (overwrites the W2 tile space; phase 1 fully done).
        {
            const float* vr = v_re + (size_t)l * NN;
            const float* vi = v_im + (size_t)l * NN;
            for (int j = tid; j < NN; j += 256) {
                float re = vr[j], im = vi[j];
                v1re[NN - 1 - j] = re;  v1im[NN - 1 - j] = -im;
                if (j > 0) { v1re[NN - 1 + j] = re;  v1im[NN - 1 + j] = im; }
            }
        }
        __syncthreads();

        for (int k0 = 0; k0 < NN; k0 += BK) {
#pragma unroll
            for (int e = tid; e < BK * BC; e += 256) {
                int kk = e >> 6;
                int c  = e & 63;
                float2 xv = xin[(size_t)(k0 + kk) * BB + (colBase + c)];
                sBre[kk][c] = xv.x;
                sBim[kk][c] = xv.y;
            }
            __syncthreads();
            const int tb = rowBase + 2 * ty + (NN - 1) - k0;  // t for p=0, kk=0
#pragma unroll 4
            for (int kk = 0; kk < BK; kk++) {
                u64 BXX[4], BYY[4];
#pragma unroll
                for (int q = 0; q < 4; q++) {
                    float bx = sBre[kk][tx + 16 * q];
                    float by = sBim[kk][tx + 16 * q];
                    BXX[q] = pk(bx, bx);
                    BYY[q] = pk(by, by);
                }
                u64 AX[2], AY[2], NAY[2];
#pragma unroll
                for (int p = 0; p < 2; p++) {
                    int t = tb + 32 * p - kk;          // in [0, 2045]; t+1 <= 2046
                    float r0 = v1re[t], r1 = v1re[t + 1];
                    float i0 = v1im[t], i1 = v1im[t + 1];
                    AX[p]  = pk(r0, r1);
                    AY[p]  = pk(i0, i1);
                    NAY[p] = pk(-i0, -i1);
                }
#pragma unroll
                for (int p = 0; p < 2; p++)
#pragma unroll
                    for (int q = 0; q < 4; q++) {
                        fma2(accRe[p][q], AX[p],  BXX[q]);
                        fma2(accRe[p][q], NAY[p], BYY[q]);
                        fma2(accIm[p][q], AX[p],  BYY[q]);
                        fma2(accIm[p][q], AY[p],  BXX[q]);
                    }
            }
            __syncthreads();
        }
    }

    // ---------------- Epilogue: complex soft-threshold + store ----------------
#pragma unroll
    for (int p = 0; p < 2; p++) {
        int r0 = rowBase + 2 * ty + 32 * p;
#pragma unroll
        for (int q = 0; q < 4; q++) {
            int c = colBase + tx + 16 * q;
            float zr0, zr1, zi0, zi1;
            upk(zr0, zr1, accRe[p][q]);
            upk(zi0, zi1, accIm[p][q]);
            float mag0 = sqrtf(zr0 * zr0 + zi0 * zi0);
            float s0 = fmaxf(mag0 - BETA, 0.f) / fmaxf(mag0, 1e-30f);
            float mag1 = sqrtf(zr1 * zr1 + zi1 * zi1);
            float s1 = fmaxf(mag1 - BETA, 0.f) / fmaxf(mag1, 1e-30f);
            xout[(size_t)r0 * BB + c]       = make_float2(zr0 * s0, zi0 * s0);
            xout[(size_t)(r0 + 1) * BB + c] = make_float2(zr1 * s1, zi1 * s1);
        }
    }
}

// Expected output = REAL PART of x, row-major, N*B float32 (confirmed R5).
__global__ void finalize_real(float* __restrict__ dst)
{
    const float2* src = g_bufB;   // layer 9 (odd) writes g_bufB
    long i = (long)blockIdx.x * blockDim.x + threadIdx.x;
    if (i < (long)NN * BB) dst[i] = src[i].x;
}

// Fallback: interleaved float view capped at n (not expected to trigger).
__global__ void finalize_interleaved(float* __restrict__ dst, long n)
{
    const float* src = (const float*)g_bufB;
    long i = (long)blockIdx.x * blockDim.x + threadIdx.x;
    long total = 2L * NN * BB;
    if (i < n && i < total) dst[i] = src[i];
}

extern "C" void kernel_launch(void* const* d_in, const int* in_sizes, int n_in,
                              void* d_out, int out_size)
{
    // Bind inputs by element count; first in size class = real part (confirmed R5).
    const float *v_re = 0, *v_im = 0, *W2_re = 0, *W2_im = 0, *y_re = 0, *y_im = 0;
    const long SV = (long)LL * NN, SW = (long)LL * NN * MM, SY = (long)MM * BB;
    for (int i = 0; i < n_in; i++) {
        const float* p = (const float*)d_in[i];
        long sz = in_sizes[i];
        if (sz == SV || sz == 4 * SV)      { if (!v_re)  v_re  = p; else v_im  = p; }
        else if (sz == SW || sz == 4 * SW) { if (!W2_re) W2_re = p; else W2_im = p; }
        else if (sz == SY || sz == 4 * SY) { if (!y_re)  y_re  = p; else y_im  = p; }
    }
    if (!v_re || !v_im || !W2_re || !W2_im || !y_re || !y_im) return;

    dim3 grid(BB / BC, NN / BR);   // (8, 16) = 128 blocks
    for (int l = 0; l < LL; l++) {
        lista_layer<<<grid, 256>>>(v_re, v_im, W2_re, W2_im, y_re, y_im, l);
    }

    const long NB = (long)NN * BB;            // 524288
    long os = out_size;
    if (os == NB || os == 4 * NB) {
        finalize_real<<<(int)((NB + 255) / 256), 256>>>((float*)d_out);
    } else {
        long nf = os < 2 * NB ? os : 2 * NB;
        finalize_interleaved<<<(int)((nf + 255) / 256), 256>>>((float*)d_out, nf);
    }
}

// round 11
// speedup vs baseline: 1.2100x; 1.2100x over previous
#include <cuda_runtime.h>
#include <cuda_bf16.h>

#define NN 1024
#define MM 256
#define BB 512
#define LL 10
#define BETA 0.01f

#define BM 128              // CTA tile in M' rows (= 64 orig rows)
#define BN 64               // CTA tile N
#define SK 8                // orig k per stage -> 48 slots
#define ABYTES 16384        // A stage: 128 rows x 128B (48 slots used, padded)
#define BBYTES 6144         // B stage: 48 rows x 128B
#define TAB_OFF 0
#define A_OFF   65536       // table: 2047*32B rounded region
#define B_OFF   (A_OFF + 2 * ABYTES)
#define SMEM_TOTAL (B_OFF + 2 * BBYTES)   // 110592

typedef unsigned u32;
typedef unsigned short u16;

// ONLY global scratch: x planes [rh, rl, ih, il], ping-pong. 2 x 4MB = 8MB (R5-proven budget).
__device__ __nv_bfloat16 gBx[2][(size_t)4 * NN * BB];

// ---------------- helpers ----------------
__device__ __forceinline__ u32 s2u(const void* p) {
    u32 a;
    asm("{ .reg .u64 t; cvta.to.shared.u64 t, %1; cvt.u32.u64 %0, t; }" : "=r"(a) : "l"(p));
    return a;
}
#define SWZ(o) ((o) ^ (((o) >> 3) & 0x70))

__device__ __forceinline__ void cpa16(u32 dst, const void* src) {
    asm volatile("cp.async.cg.shared.global [%0], [%1], 16;" :: "r"(dst), "l"(src));
}
__device__ __forceinline__ void cp_commit() {
    asm volatile("cp.async.commit_group;" ::: "memory");
}
template <int N_> __device__ __forceinline__ void cp_wait() {
    asm volatile("cp.async.wait_group %0;" :: "n"(N_) : "memory");
}
__device__ __forceinline__ void sts32(u32 a, u32 v) {
    asm volatile("st.shared.b32 [%0], %1;" :: "r"(a), "r"(v) : "memory");
}
__device__ __forceinline__ void sts128(u32 a, u32 x, u32 y, u32 z, u32 w) {
    asm volatile("st.shared.v4.b32 [%0], {%1,%2,%3,%4};"
                 :: "r"(a), "r"(x), "r"(y), "r"(z), "r"(w) : "memory");
}
__device__ __forceinline__ void lds128(u32& x, u32& y, u32& z, u32& w, u32 a) {
    asm volatile("ld.shared.v4.b32 {%0,%1,%2,%3}, [%4];"
                 : "=r"(x), "=r"(y), "=r"(z), "=r"(w) : "r"(a));
}
__device__ __forceinline__ void ldsm4(u32& r0, u32& r1, u32& r2, u32& r3, u32 a) {
    asm volatile("ldmatrix.sync.aligned.m8n8.x4.shared.b16 {%0,%1,%2,%3}, [%4];"
                 : "=r"(r0), "=r"(r1), "=r"(r2), "=r"(r3) : "r"(a));
}
__device__ __forceinline__ void ldsm4t(u32& r0, u32& r1, u32& r2, u32& r3, u32 a) {
    asm volatile("ldmatrix.sync.aligned.m8n8.x4.trans.shared.b16 {%0,%1,%2,%3}, [%4];"
                 : "=r"(r0), "=r"(r1), "=r"(r2), "=r"(r3) : "r"(a));
}
__device__ __forceinline__ void hmma(float& d0, float& d1, float& d2, float& d3,
                                     u32 a0, u32 a1, u32 a2, u32 a3, u32 b0, u32 b1) {
    asm volatile("mma.sync.aligned.m16n8k16.row.col.f32.bf16.bf16.f32 "
                 "{%0,%1,%2,%3}, {%4,%5,%6,%7}, {%8,%9}, {%0,%1,%2,%3};"
                 : "+f"(d0), "+f"(d1), "+f"(d2), "+f"(d3)
                 : "r"(a0), "r"(a1), "r"(a2), "r"(a3), "r"(b0), "r"(b1));
}
__device__ __forceinline__ void split2u(float v, u16& h, u16& lo) {
    __nv_bfloat16 hb = __float2bfloat16(v);
    h = __bfloat16_as_ushort(hb);
    lo = __bfloat16_as_ushort(__float2bfloat16(v - __bfloat162float(hb)));
}
__device__ __forceinline__ u32 pk(u16 lo, u16 hi) { return (u32)lo | ((u32)hi << 16); }

// ---------------- pre-kernel: y planes [rh, rl, ih, il] into d_out scratch ----------------
__global__ void makeBy(const float* __restrict__ y_re, const float* __restrict__ y_im,
                       float* __restrict__ dout)
{
    int e = blockIdx.x * 256 + threadIdx.x;    // over MM*BB
    int n = e & 511;
    int m = e >> 9;
    u16 rh, rl, ih, il;
    split2u(y_re[(size_t)m * BB + n], rh, rl);
    split2u(y_im[(size_t)m * BB + n], ih, il);
    __nv_bfloat16* yp = (__nv_bfloat16*)dout;
    size_t o = (size_t)m * BB + n;
    yp[o]                      = __ushort_as_bfloat16(rh);
    yp[o + (size_t)MM * BB]    = __ushort_as_bfloat16(rl);
    yp[o + (size_t)2 * MM * BB] = __ushort_as_bfloat16(ih);
    yp[o + (size_t)3 * MM * BB] = __ushort_as_bfloat16(il);
}

// ---------------- fused layer ----------------
__global__ __launch_bounds__(256, 1)
void gemm_layer(int l, int kStart, int last,
                const float* __restrict__ v_re, const float* __restrict__ v_im,
                const float* __restrict__ W2_re, const float* __restrict__ W2_im,
                float* __restrict__ dout, int cur)
{
    extern __shared__ __align__(16) char smem[];
    const u32 sb = s2u(smem);
    const int tid = threadIdx.x, wid = tid >> 5, lane = tid & 31;
    const int wm = wid & 3, wn = wid >> 2;     // warps 4x2, warp tile 32x32
    const int mBase = blockIdx.y * BM;         // M' rows
    const int nBase = blockIdx.x * BN;
    const __nv_bfloat16* Bx = gBx[cur];
    __nv_bfloat16* BxOut = gBx[cur ^ 1];
    const __nv_bfloat16* Yp = (const __nv_bfloat16*)dout;

    // Toeplitz table: per t, [T0,T1,T2,pad | T3,T4,T5,pad] (u32 each), 32B stride.
    // Re-row triplet (T0,T1,T2) = (rh,rh),(rl,nh),(nh,nl); Im (T3,T4,T5) = (ih,ih),(il,rh),(rh,rl).
    if (kStart == 0) {
        for (int t = tid; t < 2047; t += 256) {
            float zr, zi;
            if (t <= 1023) { int j = 1023 - t; zr = v_re[l * NN + j]; zi = -v_im[l * NN + j]; }
            else           { int j = t - 1023; zr = v_re[l * NN + j]; zi =  v_im[l * NN + j]; }
            u16 rh, rl, ih, il;
            split2u(zr, rh, rl);
            split2u(zi, ih, il);
            u16 nh = ih ^ 0x8000, nl = il ^ 0x8000;
            sts128(sb + TAB_OFF + t * 32,      pk(rh, rh), pk(rl, nh), pk(nh, nl), 0u);
            sts128(sb + TAB_OFF + t * 32 + 16, pk(ih, ih), pk(il, rh), pk(rh, rl), 0u);
        }
    }
    __syncthreads();

    const int ST = (1280 - kStart) / SK;

    float4 acc[2][4];
#pragma unroll
    for (int i = 0; i < 2; i++)
#pragma unroll
        for (int j = 0; j < 4; j++) { acc[i][j].x = 0.f; acc[i][j].y = 0.f; acc[i][j].z = 0.f; acc[i][j].w = 0.f; }

    // ---- builders ----
    // Toeplitz A stage: thread = (row 0..127, half 0..1); 4 consecutive k; table LDS + STS.128.
    // W2 A stage: 512 complex cells, split fp32 inline, 6x STS.32 per cell.
    // B: cp.async rows with plane map [0,1,0,2,3,2] and duplicate sources.
#define BUILD_A(dd, kk0)                                                                     \
    do {                                                                                     \
        if ((kk0) < 1024) {                                                                  \
            int row = tid >> 1, half = tid & 1;                                              \
            int origR = (mBase >> 1) + (row >> 1);                                           \
            u32 taddr = sb + TAB_OFF + (u32)((row & 1) * 16);                                \
            int tb = origR - ((kk0) + half * 4) + 1023;                                      \
            u32 x0, x1, x2, x3, y0, y1, y2, y3, z0, z1, z2, z3, w0, w1, w2, w3;              \
            lds128(x0, x1, x2, x3, taddr + (u32)tb * 32);                                    \
            lds128(y0, y1, y2, y3, taddr + (u32)(tb - 1) * 32);                              \
            lds128(z0, z1, z2, z3, taddr + (u32)(tb - 2) * 32);                              \
            lds128(w0, w1, w2, w3, taddr + (u32)(tb - 3) * 32);                              \
            u32 ab = sb + A_OFF + (dd) * ABYTES;                                             \
            u32 base = (u32)(row * 128 + half * 48);                                         \
            sts128(ab + SWZ(base),      x0, x1, x2, y0);                                     \
            sts128(ab + SWZ(base + 16), y1, y2, z0, z1);                                     \
            sts128(ab + SWZ(base + 32), z2, w0, w1, w2);                                     \
        } else {                                                                             \
            u32 ab = sb + A_OFF + (dd) * ABYTES;                                             \
            for (int rep = 0; rep < 2; rep++) {                                              \
                int q = tid + rep * 256;                                                     \
                int rloc = q >> 3, kl = q & 7;                                               \
                int origR = (mBase >> 1) + rloc;                                             \
                int kg = (kk0) - 1024 + kl;                                                  \
                float zr = W2_re[((size_t)l * NN + origR) * MM + kg];                        \
                float zi = W2_im[((size_t)l * NN + origR) * MM + kg];                        \
                u16 rh, rl2, ih, il;                                                         \
                split2u(zr, rh, rl2);                                                        \
                split2u(zi, ih, il);                                                         \
                u16 nh = ih ^ 0x8000, nl = il ^ 0x8000;                                      \
                u32 be = (u32)((2 * rloc) * 128 + kl * 12);                                  \
                u32 bo = (u32)((2 * rloc + 1) * 128 + kl * 12);                              \
                sts32(ab + SWZ(be),     pk(rh, rh));                                         \
                sts32(ab + SWZ(be + 4), pk(rl2, nh));                                        \
                sts32(ab + SWZ(be + 8), pk(nh, nl));                                         \
                sts32(ab + SWZ(bo),     pk(ih, ih));                                         \
                sts32(ab + SWZ(bo + 4), pk(il, rh));                                         \
                sts32(ab + SWZ(bo + 8), pk(rh, rl2));                                        \
            }                                                                                \
        }                                                                                    \
    } while (0)

#define LOAD_B(dd, kk0)                                                                      \
    do {                                                                                     \
        u32 bb = sb + B_OFF + (dd) * BBYTES;                                                 \
        for (int rep = 0; rep < 2; rep++) {                                                  \
            int idx = tid + rep * 256;                                                       \
            if (idx < 384) {                                                                 \
                int row = idx >> 3, seg = idx & 7;                                           \
                int qq = row / 6, jj = row - 6 * qq;                                         \
                int p = (jj == 1) ? 1 : ((jj == 4) ? 3 : ((jj <= 2) ? 0 : 2));               \
                int k = (kk0) + qq;                                                          \
                const __nv_bfloat16* src = (k < 1024)                                        \
                    ? (Bx + ((size_t)p * NN + k) * BB + nBase + seg * 8)                     \
                    : (Yp + ((size_t)p * MM + (k - 1024)) * BB + nBase + seg * 8);           \
                cpa16(bb + SWZ((u32)(row * 128 + seg * 16)), src);                           \
            }                                                                                \
        }                                                                                    \
        cp_commit();                                                                         \
    } while (0)

    BUILD_A(0, kStart);
    LOAD_B(0, kStart);

    for (int s = 0; s < ST; s++) {
        const int d = s & 1;
        if (s + 1 < ST) {
            BUILD_A(d ^ 1, kStart + (s + 1) * SK);
            LOAD_B(d ^ 1, kStart + (s + 1) * SK);
            cp_wait<1>();
        } else {
            cp_wait<0>();
        }
        __syncthreads();
        const u32 aB = sb + A_OFF + d * ABYTES;
        const u32 bB = sb + B_OFF + d * BBYTES;
#pragma unroll
        for (int kk = 0; kk < 3; kk++) {
            u32 a00, a01, a02, a03, a10, a11, a12, a13;
            u32 b00, b01, b02, b03, b10, b11, b12, b13;
            ldsm4(a00, a01, a02, a03, aB + SWZ((u32)((wm * 32 + (lane & 15)) * 128 + kk * 32 + (lane >> 4) * 16)));
            ldsm4(a10, a11, a12, a13, aB + SWZ((u32)((wm * 32 + 16 + (lane & 15)) * 128 + kk * 32 + (lane >> 4) * 16)));
            ldsm4t(b00, b01, b02, b03, bB + SWZ((u32)((kk * 16 + (lane & 15)) * 128 + wn * 64 + (lane >> 4) * 16)));
            ldsm4t(b10, b11, b12, b13, bB + SWZ((u32)((kk * 16 + (lane & 15)) * 128 + wn * 64 + 32 + (lane >> 4) * 16)));
            hmma(acc[0][0].x, acc[0][0].y, acc[0][0].z, acc[0][0].w, a00, a01, a02, a03, b00, b01);
            hmma(acc[0][1].x, acc[0][1].y, acc[0][1].z, acc[0][1].w, a00, a01, a02, a03, b02, b03);
            hmma(acc[0][2].x, acc[0][2].y, acc[0][2].z, acc[0][2].w, a00, a01, a02, a03, b10, b11);
            hmma(acc[0][3].x, acc[0][3].y, acc[0][3].z, acc[0][3].w, a00, a01, a02, a03, b12, b13);
            hmma(acc[1][0].x, acc[1][0].y, acc[1][0].z, acc[1][0].w, a10, a11, a12, a13, b00, b01);
            hmma(acc[1][1].x, acc[1][1].y, acc[1][1].z, acc[1][1].w, a10, a11, a12, a13, b02, b03);
            hmma(acc[1][2].x, acc[1][2].y, acc[1][2].z, acc[1][2].w, a10, a11, a12, a13, b10, b11);
            hmma(acc[1][3].x, acc[1][3].y, acc[1][3].z, acc[1][3].w, a10, a11, a12, a13, b12, b13);
        }
        __syncthreads();
    }

    // ---- epilogue: C -> SMEM (table region, now dead), threshold, emit planes ----
    float* sC = (float*)smem;   // [128][66]
#pragma unroll
    for (int im = 0; im < 2; im++)
#pragma unroll
        for (int jn = 0; jn < 4; jn++) {
            int r0 = wm * 32 + im * 16 + (lane >> 2);
            int c0 = wn * 32 + jn * 8 + (lane & 3) * 2;
            sC[r0 * 66 + c0]           = acc[im][jn].x;
            sC[r0 * 66 + c0 + 1]       = acc[im][jn].y;
            sC[(r0 + 8) * 66 + c0]     = acc[im][jn].z;
            sC[(r0 + 8) * 66 + c0 + 1] = acc[im][jn].w;
        }
    __syncthreads();

    const int cl = tid & 63;
    const int tr = tid >> 6;
    for (int t = tr; t < 64; t += 4) {
        float zr = sC[(2 * t) * 66 + cl];
        float zi = sC[(2 * t + 1) * 66 + cl];
        float mag = sqrtf(zr * zr + zi * zi);
        float sf = fmaxf(mag - BETA, 0.f) / fmaxf(mag, 1e-30f);
        float xr = zr * sf, xi = zi * sf;
        int R  = (mBase >> 1) + t;
        int gc = nBase + cl;
        if (last) {
            ((float*)BxOut)[(size_t)R * BB + gc] = xr;   // fp32 Re(x); finalize copies to d_out
        } else {
            u16 rh, rl, ih, il;
            split2u(xr, rh, rl);
            split2u(xi, ih, il);
            size_t o = (size_t)R * BB + gc;
            BxOut[o]                      = __ushort_as_bfloat16(rh);
            BxOut[o + (size_t)NN * BB]     = __ushort_as_bfloat16(rl);
            BxOut[o + (size_t)2 * NN * BB] = __ushort_as_bfloat16(ih);
            BxOut[o + (size_t)3 * NN * BB] = __ushort_as_bfloat16(il);
        }
    }
#undef BUILD_A
#undef LOAD_B
}

// ---------------- finalize: copy fp32 Re(x) from gBx[0] into d_out ----------------
__global__ void finalize(float* __restrict__ dst)
{
    const float* src = (const float*)gBx[0];     // layer 9 (cur=1) wrote gBx[0]
    long i = (long)blockIdx.x * 256 + threadIdx.x;
    if (i < (long)NN * BB) dst[i] = src[i];
}

extern "C" void kernel_launch(void* const* d_in, const int* in_sizes, int n_in,
                              void* d_out, int out_size)
{
    // Bind inputs by element count; first in size class = real part (confirmed R5).
    const float *v_re = 0, *v_im = 0, *W2_re = 0, *W2_im = 0, *y_re = 0, *y_im = 0;
    const long SV = (long)LL * NN, SW_ = (long)LL * NN * MM, SY = (long)MM * BB;
    for (int i = 0; i < n_in; i++) {
        const float* p = (const float*)d_in[i];
        long sz = in_sizes[i];
        if (sz == SV || sz == 4 * SV)        { if (!v_re)  v_re  = p; else v_im  = p; }
        else if (sz == SW_ || sz == 4 * SW_) { if (!W2_re) W2_re = p; else W2_im = p; }
        else if (sz == SY || sz == 4 * SY)   { if (!y_re)  y_re  = p; else y_im  = p; }
    }
    if (!v_re || !v_im || !W2_re || !W2_im || !y_re || !y_im) return;

    cudaFuncSetAttribute(gemm_layer, cudaFuncAttributeMaxDynamicSharedMemorySize, SMEM_TOTAL);

    makeBy<<<(MM * BB) / 256, 256>>>(y_re, y_im, (float*)d_out);

    dim3 grid(BB / BN, 2 * NN / BM);   // (8, 16) = 128 CTAs
    for (int l = 0; l < LL; l++) {
        int kStart = (l == 0) ? 1024 : 0;
        gemm_layer<<<grid, 256, SMEM_TOTAL>>>(l, kStart, l == LL - 1,
                                              v_re, v_im, W2_re, W2_im,
                                              (float*)d_out, l & 1);
    }
    finalize<<<(NN * BB) / 256, 256>>>((float*)d_out);
}

// round 12
// speedup vs baseline: 1.6112x; 1.3316x over previous
#include <cuda_runtime.h>
#include <cuda_bf16.h>

#define NN 1024
#define MM 256
#define BB 512
#define LL 10
#define BETA 0.01f

#define BM 128               // CTA tile in M' rows (= 64 orig rows)
#define BN 64                // CTA tile N
// super-stage = 32 orig k = 4 sub-tiles of 48 slots (128B rows)
#define TAB_OFF 0            // 1087 entries x 32B = 34784
#define A_OFF   34816        // 2 buffers x 4 subs x 16384 = 131072
#define B_OFF   165888       // 2 buffers x 4 subs x 6144  = 49152
#define SMEM_TOTAL 215040

typedef unsigned u32;
typedef unsigned short u16;

// ONLY global scratch: x planes [rh, rl, ih, il], ping-pong. 8MB total (proven budget).
__device__ __nv_bfloat16 gBx[2][(size_t)4 * NN * BB];

// ---------------- helpers ----------------
__device__ __forceinline__ u32 s2u(const void* p) {
    u32 a;
    asm("{ .reg .u64 t; cvta.to.shared.u64 t, %1; cvt.u32.u64 %0, t; }" : "=r"(a) : "l"(p));
    return a;
}
#define SWZ(o) ((o) ^ (((o) >> 3) & 0x70))

__device__ __forceinline__ void cpa16(u32 dst, const void* src) {
    asm volatile("cp.async.cg.shared.global [%0], [%1], 16;" :: "r"(dst), "l"(src));
}
__device__ __forceinline__ void cp_commit() {
    asm volatile("cp.async.commit_group;" ::: "memory");
}
template <int N_> __device__ __forceinline__ void cp_wait() {
    asm volatile("cp.async.wait_group %0;" :: "n"(N_) : "memory");
}
__device__ __forceinline__ void sts32(u32 a, u32 v) {
    asm volatile("st.shared.b32 [%0], %1;" :: "r"(a), "r"(v) : "memory");
}
__device__ __forceinline__ void sts128(u32 a, u32 x, u32 y, u32 z, u32 w) {
    asm volatile("st.shared.v4.b32 [%0], {%1,%2,%3,%4};"
                 :: "r"(a), "r"(x), "r"(y), "r"(z), "r"(w) : "memory");
}
__device__ __forceinline__ void lds128(u32& x, u32& y, u32& z, u32& w, u32 a) {
    asm volatile("ld.shared.v4.b32 {%0,%1,%2,%3}, [%4];"
                 : "=r"(x), "=r"(y), "=r"(z), "=r"(w) : "r"(a));
}
__device__ __forceinline__ void ldsm4(u32& r0, u32& r1, u32& r2, u32& r3, u32 a) {
    asm volatile("ldmatrix.sync.aligned.m8n8.x4.shared.b16 {%0,%1,%2,%3}, [%4];"
                 : "=r"(r0), "=r"(r1), "=r"(r2), "=r"(r3) : "r"(a));
}
__device__ __forceinline__ void ldsm4t(u32& r0, u32& r1, u32& r2, u32& r3, u32 a) {
    asm volatile("ldmatrix.sync.aligned.m8n8.x4.trans.shared.b16 {%0,%1,%2,%3}, [%4];"
                 : "=r"(r0), "=r"(r1), "=r"(r2), "=r"(r3) : "r"(a));
}
__device__ __forceinline__ void hmma(float& d0, float& d1, float& d2, float& d3,
                                     u32 a0, u32 a1, u32 a2, u32 a3, u32 b0, u32 b1) {
    asm volatile("mma.sync.aligned.m16n8k16.row.col.f32.bf16.bf16.f32 "
                 "{%0,%1,%2,%3}, {%4,%5,%6,%7}, {%8,%9}, {%0,%1,%2,%3};"
                 : "+f"(d0), "+f"(d1), "+f"(d2), "+f"(d3)
                 : "r"(a0), "r"(a1), "r"(a2), "r"(a3), "r"(b0), "r"(b1));
}
__device__ __forceinline__ void split2u(float v, u16& h, u16& lo) {
    __nv_bfloat16 hb = __float2bfloat16(v);
    h = __bfloat16_as_ushort(hb);
    lo = __bfloat16_as_ushort(__float2bfloat16(v - __bfloat162float(hb)));
}
__device__ __forceinline__ u32 pk(u16 lo, u16 hi) { return (u32)lo | ((u32)hi << 16); }

// ---------------- pre-kernel: y planes [rh, rl, ih, il] into d_out scratch ----------------
__global__ void makeBy(const float* __restrict__ y_re, const float* __restrict__ y_im,
                       float* __restrict__ dout)
{
    int e = blockIdx.x * 256 + threadIdx.x;    // over MM*BB
    int n = e & 511;
    int m = e >> 9;
    u16 rh, rl, ih, il;
    split2u(y_re[(size_t)m * BB + n], rh, rl);
    split2u(y_im[(size_t)m * BB + n], ih, il);
    __nv_bfloat16* yp = (__nv_bfloat16*)dout;
    size_t o = (size_t)m * BB + n;
    yp[o]                       = __ushort_as_bfloat16(rh);
    yp[o + (size_t)MM * BB]     = __ushort_as_bfloat16(rl);
    yp[o + (size_t)2 * MM * BB] = __ushort_as_bfloat16(ih);
    yp[o + (size_t)3 * MM * BB] = __ushort_as_bfloat16(il);
}

// ---------------- builders ----------------
// Toeplitz super-stage: 4 sub-tiles; thread = (M' row 0..127, half 0..1), 4 k per half.
__device__ __forceinline__ void build_toep(u32 sb, u32 abase, int kk0, int tid)
{
    const int row = tid >> 1, half = tid & 1;
    const int rl4 = row >> 1;                         // orig row local (0..63)
    const u32 taddr = sb + TAB_OFF + (u32)((row & 1) * 16);
    const u32 base = (u32)(row * 128 + half * 48);
#pragma unroll
    for (int sub = 0; sub < 4; sub++) {
        int tb = rl4 - (kk0 + 8 * sub + half * 4) + 1023;   // local table idx, >= 3
        u32 x0, x1, x2, x3, y0, y1, y2, y3, z0, z1, z2, z3, w0, w1, w2, w3;
        lds128(x0, x1, x2, x3, taddr + (u32)tb * 32);
        lds128(y0, y1, y2, y3, taddr + (u32)(tb - 1) * 32);
        lds128(z0, z1, z2, z3, taddr + (u32)(tb - 2) * 32);
        lds128(w0, w1, w2, w3, taddr + (u32)(tb - 3) * 32);
        u32 ab = abase + sub * 16384;
        sts128(ab + SWZ(base),      x0, x1, x2, y0);
        sts128(ab + SWZ(base + 16), y1, y2, z0, z1);
        sts128(ab + SWZ(base + 32), z2, w0, w1, w2);
    }
}

// W2 super-stage: per sub, 512 complex cells, split fp32 inline.
__device__ __forceinline__ void build_w2(u32 abase, int kk0, int tid, int l, int mOrig,
                                         const float* __restrict__ W2_re,
                                         const float* __restrict__ W2_im)
{
#pragma unroll
    for (int sub = 0; sub < 4; sub++) {
        u32 ab = abase + sub * 16384;
#pragma unroll
        for (int rep = 0; rep < 2; rep++) {
            int q = tid + rep * 256;
            int rloc = q >> 3, kl = q & 7;
            int origR = mOrig + rloc;
            int kg = kk0 + sub * 8 - 1024 + kl;
            float zr = W2_re[((size_t)l * NN + origR) * MM + kg];
            float zi = W2_im[((size_t)l * NN + origR) * MM + kg];
            u16 rh, rl2, ih, il;
            split2u(zr, rh, rl2);
            split2u(zi, ih, il);
            u16 nh = ih ^ 0x8000, nl = il ^ 0x8000;
            u32 be = (u32)((2 * rloc) * 128 + kl * 12);
            u32 bo = (u32)((2 * rloc + 1) * 128 + kl * 12);
            sts32(ab + SWZ(be),     pk(rh, rh));
            sts32(ab + SWZ(be + 4), pk(rl2, nh));
            sts32(ab + SWZ(be + 8), pk(nh, nl));
            sts32(ab + SWZ(bo),     pk(ih, ih));
            sts32(ab + SWZ(bo + 4), pk(il, rh));
            sts32(ab + SWZ(bo + 8), pk(rh, rl2));
        }
    }
}

// B super-stage: 192 rows x 128B via cp.async; plane map [0,1,0,2,3,2] with dup sources.
__device__ __forceinline__ void load_b(u32 bbase, int kk0, int tid, int nBase,
                                       const __nv_bfloat16* __restrict__ Bx,
                                       const __nv_bfloat16* __restrict__ Yp)
{
#pragma unroll
    for (int rep = 0; rep < 6; rep++) {
        int idx = tid + rep * 256;                // 0..1535
        int rowg = idx >> 3, seg = idx & 7;
        int sub = rowg / 48;
        int row = rowg - sub * 48;
        int qq = row / 6, jj = row - 6 * qq;
        int p = (jj == 1) ? 1 : ((jj == 4) ? 3 : ((jj <= 2) ? 0 : 2));
        int k = kk0 + sub * 8 + qq;
        const __nv_bfloat16* src = (k < 1024)
            ? (Bx + ((size_t)p * NN + k) * BB + nBase + seg * 8)
            : (Yp + ((size_t)p * MM + (k - 1024)) * BB + nBase + seg * 8);
        cpa16(bbase + sub * 6144 + SWZ((u32)(row * 128 + seg * 16)), src);
    }
    cp_commit();
}

// ---------------- fused layer ----------------
__global__ __launch_bounds__(256, 1)
void gemm_layer(int l, int kStart, int last,
                const float* __restrict__ v_re, const float* __restrict__ v_im,
                const float* __restrict__ W2_re, const float* __restrict__ W2_im,
                float* __restrict__ dout, int cur)
{
    extern __shared__ __align__(16) char smem[];
    const u32 sb = s2u(smem);
    const int tid = threadIdx.x, wid = tid >> 5, lane = tid & 31;
    const int wm = wid & 3, wn = wid >> 2;     // warps 4x2, warp tile 32x32
    const int mBase = blockIdx.y * BM;         // M' rows
    const int mOrig = mBase >> 1;
    const int nBase = blockIdx.x * BN;
    const __nv_bfloat16* Bx = gBx[cur];
    __nv_bfloat16* BxOut = gBx[cur ^ 1];
    const __nv_bfloat16* Yp = (const __nv_bfloat16*)dout;

    // Restricted Toeplitz table: local t in [0,1086] maps to global t = mOrig + tl.
    if (kStart == 0) {
        for (int tl = tid; tl < 1087; tl += 256) {
            int t = mOrig + tl;
            float zr, zi;
            if (t <= 1023) { int j = 1023 - t; zr = v_re[l * NN + j]; zi = -v_im[l * NN + j]; }
            else           { int j = t - 1023; zr = v_re[l * NN + j]; zi =  v_im[l * NN + j]; }
            u16 rh, rl, ih, il;
            split2u(zr, rh, rl);
            split2u(zi, ih, il);
            u16 nh = ih ^ 0x8000, nl = il ^ 0x8000;
            sts128(sb + TAB_OFF + tl * 32,      pk(rh, rh), pk(rl, nh), pk(nh, nl), 0u);
            sts128(sb + TAB_OFF + tl * 32 + 16, pk(ih, ih), pk(il, rh), pk(rh, rl), 0u);
        }
    }
    __syncthreads();

    const int ST = (1280 - kStart) / 32;

    float4 acc[2][4];
#pragma unroll
    for (int i = 0; i < 2; i++)
#pragma unroll
        for (int j = 0; j < 4; j++) { acc[i][j].x = 0.f; acc[i][j].y = 0.f; acc[i][j].z = 0.f; acc[i][j].w = 0.f; }

    // prologue stage 0
    if (kStart < 1024) build_toep(sb, sb + A_OFF, kStart, tid);
    else               build_w2(sb + A_OFF, kStart, tid, l, mOrig, W2_re, W2_im);
    load_b(sb + B_OFF, kStart, tid, nBase, Bx, Yp);

    for (int s = 0; s < ST; s++) {
        const int d = s & 1;
        if (s + 1 < ST) {
            int kn = kStart + (s + 1) * 32;
            u32 abn = sb + A_OFF + (d ^ 1) * 65536;
            if (kn < 1024) build_toep(sb, abn, kn, tid);
            else           build_w2(abn, kn, tid, l, mOrig, W2_re, W2_im);
            load_b(sb + B_OFF + (d ^ 1) * 24576, kn, tid, nBase, Bx, Yp);
            cp_wait<1>();
        } else {
            cp_wait<0>();
        }
        __syncthreads();
        const u32 aB = sb + A_OFF + d * 65536;
        const u32 bB = sb + B_OFF + d * 24576;
#pragma unroll
        for (int sub = 0; sub < 4; sub++) {
            const u32 aBs = aB + sub * 16384;
            const u32 bBs = bB + sub * 6144;
            u32 fa0[3][4], fa1[3][4], fb0[3][4], fb1[3][4];
#pragma unroll
            for (int kk = 0; kk < 3; kk++) {
                ldsm4(fa0[kk][0], fa0[kk][1], fa0[kk][2], fa0[kk][3],
                      aBs + SWZ((u32)((wm * 32 + (lane & 15)) * 128 + kk * 32 + (lane >> 4) * 16)));
                ldsm4(fa1[kk][0], fa1[kk][1], fa1[kk][2], fa1[kk][3],
                      aBs + SWZ((u32)((wm * 32 + 16 + (lane & 15)) * 128 + kk * 32 + (lane >> 4) * 16)));
                ldsm4t(fb0[kk][0], fb0[kk][1], fb0[kk][2], fb0[kk][3],
                       bBs + SWZ((u32)((kk * 16 + (lane & 15)) * 128 + wn * 64 + (lane >> 4) * 16)));
                ldsm4t(fb1[kk][0], fb1[kk][1], fb1[kk][2], fb1[kk][3],
                       bBs + SWZ((u32)((kk * 16 + (lane & 15)) * 128 + wn * 64 + 32 + (lane >> 4) * 16)));
            }
#pragma unroll
            for (int kk = 0; kk < 3; kk++) {
                hmma(acc[0][0].x, acc[0][0].y, acc[0][0].z, acc[0][0].w,
                     fa0[kk][0], fa0[kk][1], fa0[kk][2], fa0[kk][3], fb0[kk][0], fb0[kk][1]);
                hmma(acc[0][1].x, acc[0][1].y, acc[0][1].z, acc[0][1].w,
                     fa0[kk][0], fa0[kk][1], fa0[kk][2], fa0[kk][3], fb0[kk][2], fb0[kk][3]);
                hmma(acc[0][2].x, acc[0][2].y, acc[0][2].z, acc[0][2].w,
                     fa0[kk][0], fa0[kk][1], fa0[kk][2], fa0[kk][3], fb1[kk][0], fb1[kk][1]);
                hmma(acc[0][3].x, acc[0][3].y, acc[0][3].z, acc[0][3].w,
                     fa0[kk][0], fa0[kk][1], fa0[kk][2], fa0[kk][3], fb1[kk][2], fb1[kk][3]);
                hmma(acc[1][0].x, acc[1][0].y, acc[1][0].z, acc[1][0].w,
                     fa1[kk][0], fa1[kk][1], fa1[kk][2], fa1[kk][3], fb0[kk][0], fb0[kk][1]);
                hmma(acc[1][1].x, acc[1][1].y, acc[1][1].z, acc[1][1].w,
                     fa1[kk][0], fa1[kk][1], fa1[kk][2], fa1[kk][3], fb0[kk][2], fb0[kk][3]);
                hmma(acc[1][2].x, acc[1][2].y, acc[1][2].z, acc[1][2].w,
                     fa1[kk][0], fa1[kk][1], fa1[kk][2], fa1[kk][3], fb1[kk][0], fb1[kk][1]);
                hmma(acc[1][3].x, acc[1][3].y, acc[1][3].z, acc[1][3].w,
                     fa1[kk][0], fa1[kk][1], fa1[kk][2], fa1[kk][3], fb1[kk][2], fb1[kk][3]);
            }
        }
        __syncthreads();
    }

    // ---- epilogue: C -> SMEM (table region, now dead), threshold, emit planes ----
    float* sC = (float*)smem;   // [128][66] = 33792B <= 34816
#pragma unroll
    for (int im = 0; im < 2; im++)
#pragma unroll
        for (int jn = 0; jn < 4; jn++) {
            int r0 = wm * 32 + im * 16 + (lane >> 2);
            int c0 = wn * 32 + jn * 8 + (lane & 3) * 2;
            sC[r0 * 66 + c0]           = acc[im][jn].x;
            sC[r0 * 66 + c0 + 1]       = acc[im][jn].y;
            sC[(r0 + 8) * 66 + c0]     = acc[im][jn].z;
            sC[(r0 + 8) * 66 + c0 + 1] = acc[im][jn].w;
        }
    __syncthreads();

    const int cl = tid & 63;
    const int tr = tid >> 6;
    for (int t = tr; t < 64; t += 4) {
        float zr = sC[(2 * t) * 66 + cl];
        float zi = sC[(2 * t + 1) * 66 + cl];
        float mag = sqrtf(zr * zr + zi * zi);
        float sf = fmaxf(mag - BETA, 0.f) / fmaxf(mag, 1e-30f);
        float xr = zr * sf, xi = zi * sf;
        int R  = mOrig + t;
        int gc = nBase + cl;
        if (last) {
            ((float*)BxOut)[(size_t)R * BB + gc] = xr;   // fp32 Re(x); finalize copies out
        } else {
            u16 rh, rl, ih, il;
            split2u(xr, rh, rl);
            split2u(xi, ih, il);
            size_t o = (size_t)R * BB + gc;
            BxOut[o]                       = __ushort_as_bfloat16(rh);
            BxOut[o + (size_t)NN * BB]     = __ushort_as_bfloat16(rl);
            BxOut[o + (size_t)2 * NN * BB] = __ushort_as_bfloat16(ih);
            BxOut[o + (size_t)3 * NN * BB] = __ushort_as_bfloat16(il);
        }
    }
}

// ---------------- finalize: copy fp32 Re(x) from gBx[0] into d_out ----------------
__global__ void finalize(float* __restrict__ dst)
{
    const float* src = (const float*)gBx[0];     // layer 9 (cur=1) wrote gBx[0]
    long i = (long)blockIdx.x * 256 + threadIdx.x;
    if (i < (long)NN * BB) dst[i] = src[i];
}

extern "C" void kernel_launch(void* const* d_in, const int* in_sizes, int n_in,
                              void* d_out, int out_size)
{
    // Bind inputs by element count; first in size class = real part (confirmed R5).
    const float *v_re = 0, *v_im = 0, *W2_re = 0, *W2_im = 0, *y_re = 0, *y_im = 0;
    const long SV = (long)LL * NN, SW_ = (long)LL * NN * MM, SY = (long)MM * BB;
    for (int i = 0; i < n_in; i++) {
        const float* p = (const float*)d_in[i];
        long sz = in_sizes[i];
        if (sz == SV || sz == 4 * SV)        { if (!v_re)  v_re  = p; else v_im  = p; }
        else if (sz == SW_ || sz == 4 * SW_) { if (!W2_re) W2_re = p; else W2_im = p; }
        else if (sz == SY || sz == 4 * SY)   { if (!y_re)  y_re  = p; else y_im  = p; }
    }
    if (!v_re || !v_im || !W2_re || !W2_im || !y_re || !y_im) return;

    cudaFuncSetAttribute(gemm_layer, cudaFuncAttributeMaxDynamicSharedMemorySize, SMEM_TOTAL);

    makeBy<<<(MM * BB) / 256, 256>>>(y_re, y_im, (float*)d_out);

    dim3 grid(BB / BN, 2 * NN / BM);   // (8, 16) = 128 CTAs
    for (int l = 0; l < LL; l++) {
        int kStart = (l == 0) ? 1024 : 0;
        gemm_layer<<<grid, 256, SMEM_TOTAL>>>(l, kStart, l == LL - 1,
                                              v_re, v_im, W2_re, W2_im,
                                              (float*)d_out, l & 1);
    }
    finalize<<<(NN * BB) / 256, 256>>>((float*)d_out);
}

// round 13
// speedup vs baseline: 1.8383x; 1.1410x over previous
#include <cuda_runtime.h>
#include <cuda_bf16.h>

#define NN 1024
#define MM 256
#define BB 512
#define LL 10
#define BETA 0.01f

#define SK 16                 // orig k per stage
#define TAB_OFF 0             // 1087 entries x 32B = 34784 (pad to 34816)
#define W2A_OFF 34816         // 2 stages x 34816 (64 rows x 544B)
#define W2A_STAGE 34816
#define B_OFF   104448        // 4-deep ring x 16384 (128 slot-rows x 128B)
#define B_STAGE 16384
#define SMEM_TOTAL 169984

typedef unsigned u32;
typedef unsigned short u16;

// ONLY global scratch: x planes [rh, rl, ih, il], ping-pong. 8MB total (proven budget).
__device__ __nv_bfloat16 gBx[2][(size_t)4 * NN * BB];

// ---------------- helpers ----------------
__device__ __forceinline__ u32 s2u(const void* p) {
    u32 a;
    asm("{ .reg .u64 t; cvta.to.shared.u64 t, %1; cvt.u32.u64 %0, t; }" : "=r"(a) : "l"(p));
    return a;
}
#define SWZ(o) ((o) ^ (((o) >> 3) & 0x70))

__device__ __forceinline__ void cpa16(u32 dst, const void* src) {
    asm volatile("cp.async.cg.shared.global [%0], [%1], 16;" :: "r"(dst), "l"(src));
}
__device__ __forceinline__ void cp_commit() {
    asm volatile("cp.async.commit_group;" ::: "memory");
}
template <int N_> __device__ __forceinline__ void cp_wait() {
    asm volatile("cp.async.wait_group %0;" :: "n"(N_) : "memory");
}
__device__ __forceinline__ void sts128(u32 a, u32 x, u32 y, u32 z, u32 w) {
    asm volatile("st.shared.v4.b32 [%0], {%1,%2,%3,%4};"
                 :: "r"(a), "r"(x), "r"(y), "r"(z), "r"(w) : "memory");
}
__device__ __forceinline__ void ldsm4(u32& r0, u32& r1, u32& r2, u32& r3, u32 a) {
    asm volatile("ldmatrix.sync.aligned.m8n8.x4.shared.b16 {%0,%1,%2,%3}, [%4];"
                 : "=r"(r0), "=r"(r1), "=r"(r2), "=r"(r3) : "r"(a));
}
__device__ __forceinline__ void ldsm4t(u32& r0, u32& r1, u32& r2, u32& r3, u32 a) {
    asm volatile("ldmatrix.sync.aligned.m8n8.x4.trans.shared.b16 {%0,%1,%2,%3}, [%4];"
                 : "=r"(r0), "=r"(r1), "=r"(r2), "=r"(r3) : "r"(a));
}
__device__ __forceinline__ void hmma(float& d0, float& d1, float& d2, float& d3,
                                     u32 a0, u32 a1, u32 a2, u32 a3, u32 b0, u32 b1) {
    asm volatile("mma.sync.aligned.m16n8k16.row.col.f32.bf16.bf16.f32 "
                 "{%0,%1,%2,%3}, {%4,%5,%6,%7}, {%8,%9}, {%0,%1,%2,%3};"
                 : "+f"(d0), "+f"(d1), "+f"(d2), "+f"(d3)
                 : "r"(a0), "r"(a1), "r"(a2), "r"(a3), "r"(b0), "r"(b1));
}
__device__ __forceinline__ void split2u(float v, u16& h, u16& lo) {
    __nv_bfloat16 hb = __float2bfloat16(v);
    h = __bfloat16_as_ushort(hb);
    lo = __bfloat16_as_ushort(__float2bfloat16(v - __bfloat162float(hb)));
}
__device__ __forceinline__ u32 pk(u16 lo, u16 hi) { return (u32)lo | ((u32)hi << 16); }

// ---------------- pre-kernel: y planes [rh, rl, ih, il] into d_out scratch ----------------
__global__ void makeBy(const float* __restrict__ y_re, const float* __restrict__ y_im,
                       float* __restrict__ dout)
{
    int e = blockIdx.x * 256 + threadIdx.x;    // over MM*BB
    int n = e & 511;
    int m = e >> 9;
    u16 rh, rl, ih, il;
    split2u(y_re[(size_t)m * BB + n], rh, rl);
    split2u(y_im[(size_t)m * BB + n], ih, il);
    __nv_bfloat16* yp = (__nv_bfloat16*)dout;
    size_t o = (size_t)m * BB + n;
    yp[o]                       = __ushort_as_bfloat16(rh);
    yp[o + (size_t)MM * BB]     = __ushort_as_bfloat16(rl);
    yp[o + (size_t)2 * MM * BB] = __ushort_as_bfloat16(ih);
    yp[o + (size_t)3 * MM * BB] = __ushort_as_bfloat16(il);
}

// ---------------- B stage: 16 k x 8 slot-rows x 128B via cp.async ----------------
// slot j -> plane [xrh,xrl,xrh,xrl, xih,xil,xih,xil] = (j&1) + ((j>>2)<<1)
__device__ __forceinline__ void load_b(u32 bstage, int k0, int tid, int nBase,
                                       const __nv_bfloat16* __restrict__ Bx,
                                       const __nv_bfloat16* __restrict__ Yp)
{
#pragma unroll
    for (int rep = 0; rep < 4; rep++) {
        int idx = tid + rep * 256;
        int row = idx >> 3, seg = idx & 7;
        int k = k0 + (row >> 3);
        int j = row & 7;
        int p = (j & 1) + ((j >> 2) << 1);
        const __nv_bfloat16* src = (k < 1024)
            ? (Bx + ((size_t)p * NN + k) * BB + nBase + seg * 8)
            : (Yp + ((size_t)p * MM + (k - 1024)) * BB + nBase + seg * 8);
        cpa16(bstage + SWZ((u32)(row * 128 + seg * 16)), src);
    }
    cp_commit();
}

// ---------------- W2 A stage: 64 rows x 16 k, 32B entries, 544B row stride ----------------
__device__ __forceinline__ void build_w2(u32 w2base, int k0, int tid, int l, int mOrig,
                                         const float* __restrict__ W2_re,
                                         const float* __restrict__ W2_im)
{
#pragma unroll
    for (int rep = 0; rep < 4; rep++) {
        int q = tid + rep * 256;
        int rl = q >> 4, dk = q & 15;
        int kg = k0 + dk - 1024;
        size_t g = ((size_t)l * NN + mOrig + rl) * MM + kg;
        float zr = W2_re[g], zi = W2_im[g];
        u16 rh, rl2, ih, il;
        split2u(zr, rh, rl2);
        split2u(zi, ih, il);
        u16 nh = ih ^ 0x8000, nl = il ^ 0x8000;
        u32 base = w2base + (u32)rl * 544 + (u32)dk * 32;
        sts128(base,      pk(rh, rh), pk(rl2, rl2), pk(nh, nh), pk(nl, nl));
        sts128(base + 16, pk(ih, ih), pk(il, il),   pk(rh, rh), pk(rl2, rl2));
    }
}

// ---------------- fused layer ----------------
__global__ __launch_bounds__(256, 1)
void gemm_layer(int l, int kStart, int last,
                const float* __restrict__ v_re, const float* __restrict__ v_im,
                const float* __restrict__ W2_re, const float* __restrict__ W2_im,
                float* __restrict__ dout, int cur)
{
    extern __shared__ __align__(16) char smem[];
    const u32 sb = s2u(smem);
    const int tid = threadIdx.x, wid = tid >> 5, lane = tid & 31;
    const int wm = wid & 3, wn = wid >> 2;     // warps 4x2, warp tile 32(M')x32(N)
    const int mOrig = blockIdx.y * 64;         // orig rows covered: [mOrig, mOrig+64)
    const int nBase = blockIdx.x * 64;
    const __nv_bfloat16* Bx = gBx[cur];
    __nv_bfloat16* BxOut = gBx[cur ^ 1];
    const __nv_bfloat16* Yp = (const __nv_bfloat16*)dout;

    // Static Toeplitz table: entry tl (t = mOrig + tl): [Re 16B | Im 16B]
    // Re = [rh,rh,rl,rl, nh,nh,nl,nl], Im = [ih,ih,il,il, rh,rh,rl,rl]
    if (kStart == 0) {
        for (int tl = tid; tl < 1087; tl += 256) {
            int t = mOrig + tl;
            float zr, zi;
            if (t <= 1023) { int j = 1023 - t; zr = v_re[l * NN + j]; zi = -v_im[l * NN + j]; }
            else           { int j = t - 1023; zr = v_re[l * NN + j]; zi =  v_im[l * NN + j]; }
            u16 rh, rl, ih, il;
            split2u(zr, rh, rl);
            split2u(zi, ih, il);
            u16 nh = ih ^ 0x8000, nl = il ^ 0x8000;
            sts128(sb + TAB_OFF + tl * 32,      pk(rh, rh), pk(rl, rl), pk(nh, nh), pk(nl, nl));
            sts128(sb + TAB_OFF + tl * 32 + 16, pk(ih, ih), pk(il, il), pk(rh, rh), pk(rl, rl));
        }
    }

    const int ST = (1280 - kStart) / SK;

    // Per-thread A lane bases. Frag h rows: Rl = wm*32 + h*16 + (lane&15).
    const int Rl0 = wm * 32 + (lane & 15), Rl1 = Rl0 + 16;
    const int rl0 = Rl0 >> 1, rl1 = Rl1 >> 1;
    const int ty0 = Rl0 & 1,  ty1 = Rl1 & 1;
    const u32 khalf = (u32)(lane >> 4);
    // Toeplitz: addr(k) = tb - k*32 (entry tl = rl - k + 1023; second k-half -> -32)
    const u32 tb0 = sb + TAB_OFF + (u32)(rl0 + 1023) * 32 + (u32)ty0 * 16 - khalf * 32;
    const u32 tb1 = sb + TAB_OFF + (u32)(rl1 + 1023) * 32 + (u32)ty1 * 16 - khalf * 32;
    // W2: addr(dk) = w2stage + wb + dk*32
    const u32 wb0 = (u32)rl0 * 544 + (u32)ty0 * 16 + khalf * 32;
    const u32 wb1 = (u32)rl1 * 544 + (u32)ty1 * 16 + khalf * 32;
    // B: swizzled lane offsets (chunk cc adds cc*2048, swizzle-invariant)
    const u32 bl = (u32)((lane & 15) * 128 + wn * 64 + (int)khalf * 16);
    const u32 sB0 = SWZ(bl);
    const u32 sB1 = SWZ(bl + 32);

    float4 acc[2][4];
#pragma unroll
    for (int i = 0; i < 2; i++)
#pragma unroll
        for (int j = 0; j < 4; j++) { acc[i][j].x = 0.f; acc[i][j].y = 0.f; acc[i][j].z = 0.f; acc[i][j].w = 0.f; }

    // Prologue: 3 B stages in flight; W2 A stage 0 if layer 0
    load_b(sb + B_OFF + 0 * B_STAGE, kStart + 0 * SK, tid, nBase, Bx, Yp);
    load_b(sb + B_OFF + 1 * B_STAGE, kStart + 1 * SK, tid, nBase, Bx, Yp);
    load_b(sb + B_OFF + 2 * B_STAGE, kStart + 2 * SK, tid, nBase, Bx, Yp);
    if (kStart >= 1024) build_w2(sb + W2A_OFF, kStart, tid, l, mOrig, W2_re, W2_im);

    for (int s = 0; s < ST; s++) {
        cp_wait<2>();            // group s complete (3-ahead issue, uniform empty tail)
        __syncthreads();         // B(s) visible; all warps done with stage s-1
        if (s + 3 < ST) load_b(sb + B_OFF + ((s + 3) & 3) * B_STAGE,
                               kStart + (s + 3) * SK, tid, nBase, Bx, Yp);
        else            cp_commit();   // keep group arithmetic uniform
        const int kn = kStart + (s + 1) * SK;
        if (s + 1 < ST && kn >= 1024)
            build_w2(sb + W2A_OFF + ((s + 1) & 1) * W2A_STAGE, kn, tid, l, mOrig, W2_re, W2_im);

        const int k0 = kStart + s * SK;
        const bool toep = (k0 < 1024);
        const u32 bcur = sb + B_OFF + (s & 3) * B_STAGE;
        u32 a0base, a1base;
        if (toep) { a0base = tb0 - (u32)k0 * 32; a1base = tb1 - (u32)k0 * 32; }
        else {
            const u32 w2cur = sb + W2A_OFF + (s & 1) * W2A_STAGE;
            a0base = w2cur + wb0; a1base = w2cur + wb1;
        }

#pragma unroll
        for (int g = 0; g < 4; g++) {          // 4 groups x 2 chunks (chunk = 2 orig k)
            u32 fa0[2][4], fa1[2][4], fb0[2][4], fb1[2][4];
#pragma unroll
            for (int cc = 0; cc < 2; cc++) {
                const int c = g * 2 + cc;
                u32 aa0, aa1;
                if (toep) { aa0 = a0base - (u32)c * 64; aa1 = a1base - (u32)c * 64; }
                else      { aa0 = a0base + (u32)c * 64; aa1 = a1base + (u32)c * 64; }
                ldsm4(fa0[cc][0], fa0[cc][1], fa0[cc][2], fa0[cc][3], aa0);
                ldsm4(fa1[cc][0], fa1[cc][1], fa1[cc][2], fa1[cc][3], aa1);
                const u32 bb = bcur + (u32)c * 2048;
                ldsm4t(fb0[cc][0], fb0[cc][1], fb0[cc][2], fb0[cc][3], bb + sB0);
                ldsm4t(fb1[cc][0], fb1[cc][1], fb1[cc][2], fb1[cc][3], bb + sB1);
            }
#pragma unroll
            for (int cc = 0; cc < 2; cc++) {
                hmma(acc[0][0].x, acc[0][0].y, acc[0][0].z, acc[0][0].w,
                     fa0[cc][0], fa0[cc][1], fa0[cc][2], fa0[cc][3], fb0[cc][0], fb0[cc][1]);
                hmma(acc[0][1].x, acc[0][1].y, acc[0][1].z, acc[0][1].w,
                     fa0[cc][0], fa0[cc][1], fa0[cc][2], fa0[cc][3], fb0[cc][2], fb0[cc][3]);
                hmma(acc[0][2].x, acc[0][2].y, acc[0][2].z, acc[0][2].w,
                     fa0[cc][0], fa0[cc][1], fa0[cc][2], fa0[cc][3], fb1[cc][0], fb1[cc][1]);
                hmma(acc[0][3].x, acc[0][3].y, acc[0][3].z, acc[0][3].w,
                     fa0[cc][0], fa0[cc][1], fa0[cc][2], fa0[cc][3], fb1[cc][2], fb1[cc][3]);
                hmma(acc[1][0].x, acc[1][0].y, acc[1][0].z, acc[1][0].w,
                     fa1[cc][0], fa1[cc][1], fa1[cc][2], fa1[cc][3], fb0[cc][0], fb0[cc][1]);
                hmma(acc[1][1].x, acc[1][1].y, acc[1][1].z, acc[1][1].w,
                     fa1[cc][0], fa1[cc][1], fa1[cc][2], fa1[cc][3], fb0[cc][2], fb0[cc][3]);
                hmma(acc[1][2].x, acc[1][2].y, acc[1][2].z, acc[1][2].w,
                     fa1[cc][0], fa1[cc][1], fa1[cc][2], fa1[cc][3], fb1[cc][0], fb1[cc][1]);
                hmma(acc[1][3].x, acc[1][3].y, acc[1][3].z, acc[1][3].w,
                     fa1[cc][0], fa1[cc][1], fa1[cc][2], fa1[cc][3], fb1[cc][2], fb1[cc][3]);
            }
        }
    }
    __syncthreads();   // all warps done before sC overwrites the table region

    // ---- epilogue: C -> SMEM (table region dead), threshold, emit planes ----
    float* sC = (float*)smem;   // [128][66] = 33792B <= 34816
#pragma unroll
    for (int im = 0; im < 2; im++)
#pragma unroll
        for (int jn = 0; jn < 4; jn++) {
            int r0 = wm * 32 + im * 16 + (lane >> 2);
            int c0 = wn * 32 + jn * 8 + (lane & 3) * 2;
            sC[r0 * 66 + c0]           = acc[im][jn].x;
            sC[r0 * 66 + c0 + 1]       = acc[im][jn].y;
            sC[(r0 + 8) * 66 + c0]     = acc[im][jn].z;
            sC[(r0 + 8) * 66 + c0 + 1] = acc[im][jn].w;
        }
    __syncthreads();

    const int cl = tid & 63;
    const int tr = tid >> 6;
    for (int t = tr; t < 64; t += 4) {
        float zr = sC[(2 * t) * 66 + cl];
        float zi = sC[(2 * t + 1) * 66 + cl];
        float mag = sqrtf(zr * zr + zi * zi);
        float sf = fmaxf(mag - BETA, 0.f) / fmaxf(mag, 1e-30f);
        float xr = zr * sf, xi = zi * sf;
        int R  = mOrig + t;
        int gc = nBase + cl;
        if (last) {
            ((float*)BxOut)[(size_t)R * BB + gc] = xr;   // fp32 Re(x); finalize copies out
        } else {
            u16 rh, rl, ih, il;
            split2u(xr, rh, rl);
            split2u(xi, ih, il);
            size_t o = (size_t)R * BB + gc;
            BxOut[o]                       = __ushort_as_bfloat16(rh);
            BxOut[o + (size_t)NN * BB]     = __ushort_as_bfloat16(rl);
            BxOut[o + (size_t)2 * NN * BB] = __ushort_as_bfloat16(ih);
            BxOut[o + (size_t)3 * NN * BB] = __ushort_as_bfloat16(il);
        }
    }
}

// ---------------- finalize: copy fp32 Re(x) from gBx[0] into d_out ----------------
__global__ void finalize(float* __restrict__ dst)
{
    const float* src = (const float*)gBx[0];     // layer 9 (cur=1) wrote gBx[0]
    long i = (long)blockIdx.x * 256 + threadIdx.x;
    if (i < (long)NN * BB) dst[i] = src[i];
}

extern "C" void kernel_launch(void* const* d_in, const int* in_sizes, int n_in,
                              void* d_out, int out_size)
{
    // Bind inputs by element count; first in size class = real part (confirmed R5).
    const float *v_re = 0, *v_im = 0, *W2_re = 0, *W2_im = 0, *y_re = 0, *y_im = 0;
    const long SV = (long)LL * NN, SW_ = (long)LL * NN * MM, SY = (long)MM * BB;
    for (int i = 0; i < n_in; i++) {
        const float* p = (const float*)d_in[i];
        long sz = in_sizes[i];
        if (sz == SV || sz == 4 * SV)        { if (!v_re)  v_re  = p; else v_im  = p; }
        else if (sz == SW_ || sz == 4 * SW_) { if (!W2_re) W2_re = p; else W2_im = p; }
        else if (sz == SY || sz == 4 * SY)   { if (!y_re)  y_re  = p; else y_im  = p; }
    }
    if (!v_re || !v_im || !W2_re || !W2_im || !y_re || !y_im) return;

    cudaFuncSetAttribute(gemm_layer, cudaFuncAttributeMaxDynamicSharedMemorySize, SMEM_TOTAL);

    makeBy<<<(MM * BB) / 256, 256>>>(y_re, y_im, (float*)d_out);

    dim3 grid(BB / 64, NN / 64);   // (8, 16) = 128 CTAs
    for (int l = 0; l < LL; l++) {
        int kStart = (l == 0) ? 1024 : 0;
        gemm_layer<<<grid, 256, SMEM_TOTAL>>>(l, kStart, l == LL - 1,
                                              v_re, v_im, W2_re, W2_im,
                                              (float*)d_out, l & 1);
    }
    finalize<<<(NN * BB) / 256, 256>>>((float*)d_out);
}

// round 14
// speedup vs baseline: 1.9927x; 1.0840x over previous
#include <cuda_runtime.h>
#include <cuda_bf16.h>

#define NN 1024
#define MM 256
#define BB 512
#define LL 10
#define BETA 0.01f

#define SK 32                 // orig k per stage
#define TAB_OFF 0             // 1087 entries x 32B = 34784 (pad 34816)
#define W2A_OFF 34816         // single stage: 64 rows x 1056B = 67584
#define B_OFF   102400        // 2-deep ring x 32768 (256 slot-rows x 128B)
#define B_STAGE 32768
#define SMEM_TOTAL 167936

typedef unsigned u32;
typedef unsigned short u16;

// ONLY global scratch: x planes [rh, rl, ih, il], ping-pong. 8MB total (proven budget).
__device__ __nv_bfloat16 gBx[2][(size_t)4 * NN * BB];

// ---------------- helpers ----------------
__device__ __forceinline__ u32 s2u(const void* p) {
    u32 a;
    asm("{ .reg .u64 t; cvta.to.shared.u64 t, %1; cvt.u32.u64 %0, t; }" : "=r"(a) : "l"(p));
    return a;
}
#define SWZ(o) ((o) ^ (((o) >> 3) & 0x70))

__device__ __forceinline__ void cpa16(u32 dst, const void* src) {
    asm volatile("cp.async.cg.shared.global [%0], [%1], 16;" :: "r"(dst), "l"(src));
}
__device__ __forceinline__ void cp_commit() {
    asm volatile("cp.async.commit_group;" ::: "memory");
}
template <int N_> __device__ __forceinline__ void cp_wait() {
    asm volatile("cp.async.wait_group %0;" :: "n"(N_) : "memory");
}
__device__ __forceinline__ void sts128(u32 a, u32 x, u32 y, u32 z, u32 w) {
    asm volatile("st.shared.v4.b32 [%0], {%1,%2,%3,%4};"
                 :: "r"(a), "r"(x), "r"(y), "r"(z), "r"(w) : "memory");
}
__device__ __forceinline__ void ldsm4(u32& r0, u32& r1, u32& r2, u32& r3, u32 a) {
    asm volatile("ldmatrix.sync.aligned.m8n8.x4.shared.b16 {%0,%1,%2,%3}, [%4];"
                 : "=r"(r0), "=r"(r1), "=r"(r2), "=r"(r3) : "r"(a));
}
__device__ __forceinline__ void ldsm4t(u32& r0, u32& r1, u32& r2, u32& r3, u32 a) {
    asm volatile("ldmatrix.sync.aligned.m8n8.x4.trans.shared.b16 {%0,%1,%2,%3}, [%4];"
                 : "=r"(r0), "=r"(r1), "=r"(r2), "=r"(r3) : "r"(a));
}
__device__ __forceinline__ void hmma(float& d0, float& d1, float& d2, float& d3,
                                     u32 a0, u32 a1, u32 a2, u32 a3, u32 b0, u32 b1) {
    asm volatile("mma.sync.aligned.m16n8k16.row.col.f32.bf16.bf16.f32 "
                 "{%0,%1,%2,%3}, {%4,%5,%6,%7}, {%8,%9}, {%0,%1,%2,%3};"
                 : "+f"(d0), "+f"(d1), "+f"(d2), "+f"(d3)
                 : "r"(a0), "r"(a1), "r"(a2), "r"(a3), "r"(b0), "r"(b1));
}
__device__ __forceinline__ void split2u(float v, u16& h, u16& lo) {
    __nv_bfloat16 hb = __float2bfloat16(v);
    h = __bfloat16_as_ushort(hb);
    lo = __bfloat16_as_ushort(__float2bfloat16(v - __bfloat162float(hb)));
}
__device__ __forceinline__ u32 pk(u16 lo, u16 hi) { return (u32)lo | ((u32)hi << 16); }

// ---------------- pre-kernel: y planes [rh, rl, ih, il] into d_out scratch ----------------
__global__ void makeBy(const float* __restrict__ y_re, const float* __restrict__ y_im,
                       float* __restrict__ dout)
{
    int e = blockIdx.x * 256 + threadIdx.x;    // over MM*BB
    int n = e & 511;
    int m = e >> 9;
    u16 rh, rl, ih, il;
    split2u(y_re[(size_t)m * BB + n], rh, rl);
    split2u(y_im[(size_t)m * BB + n], ih, il);
    __nv_bfloat16* yp = (__nv_bfloat16*)dout;
    size_t o = (size_t)m * BB + n;
    yp[o]                       = __ushort_as_bfloat16(rh);
    yp[o + (size_t)MM * BB]     = __ushort_as_bfloat16(rl);
    yp[o + (size_t)2 * MM * BB] = __ushort_as_bfloat16(ih);
    yp[o + (size_t)3 * MM * BB] = __ushort_as_bfloat16(il);
}

// ---------------- B stage: 32 k x 8 slot-rows x 128B via cp.async ----------------
// slot j -> plane [xrh,xrl,xrh,xrl, xih,xil,xih,xil] = (j&1) + ((j>>2)<<1)
__device__ __forceinline__ void load_b(u32 bstage, int k0, int tid, int nBase,
                                       const __nv_bfloat16* __restrict__ Bx,
                                       const __nv_bfloat16* __restrict__ Yp)
{
#pragma unroll
    for (int rep = 0; rep < 8; rep++) {
        int idx = tid + rep * 256;
        int row = idx >> 3, seg = idx & 7;
        int k = k0 + (row >> 3);
        int j = row & 7;
        int p = (j & 1) + ((j >> 2) << 1);
        const __nv_bfloat16* src = (k < 1024)
            ? (Bx + ((size_t)p * NN + k) * BB + nBase + seg * 8)
            : (Yp + ((size_t)p * MM + (k - 1024)) * BB + nBase + seg * 8);
        cpa16(bstage + SWZ((u32)(row * 128 + seg * 16)), src);
    }
    cp_commit();
}

// ---------------- W2 A stage (single buffer): 64 rows x 32 k, 32B entries, 1056B stride ----
__device__ __forceinline__ void build_w2(u32 w2base, int k0, int tid, int l, int mOrig,
                                         const float* __restrict__ W2_re,
                                         const float* __restrict__ W2_im)
{
#pragma unroll
    for (int rep = 0; rep < 8; rep++) {
        int q = tid + rep * 256;
        int rl = q >> 5, dk = q & 31;
        int kg = k0 + dk - 1024;
        size_t g = ((size_t)l * NN + mOrig + rl) * MM + kg;
        float zr = W2_re[g], zi = W2_im[g];
        u16 rh, rl2, ih, il;
        split2u(zr, rh, rl2);
        split2u(zi, ih, il);
        u16 nh = ih ^ 0x8000, nl = il ^ 0x8000;
        u32 base = w2base + (u32)rl * 1056 + (u32)dk * 32;
        sts128(base,      pk(rh, rh), pk(rl2, rl2), pk(nh, nh), pk(nl, nl));
        sts128(base + 16, pk(ih, ih), pk(il, il),   pk(rh, rh), pk(rl2, rl2));
    }
}

// ---------------- fused layer ----------------
__global__ __launch_bounds__(256, 1)
void gemm_layer(int l, int kStart, int last,
                const float* __restrict__ v_re, const float* __restrict__ v_im,
                const float* __restrict__ W2_re, const float* __restrict__ W2_im,
                float* __restrict__ dout, int cur)
{
    extern __shared__ __align__(16) char smem[];
    const u32 sb = s2u(smem);
    const int tid = threadIdx.x, wid = tid >> 5, lane = tid & 31;
    const int wm = wid & 3, wn = wid >> 2;     // warps 4x2, warp tile 32(M')x32(N)
    const int mOrig = blockIdx.y * 64;
    const int nBase = blockIdx.x * 64;
    const __nv_bfloat16* Bx = gBx[cur];
    __nv_bfloat16* BxOut = gBx[cur ^ 1];
    const __nv_bfloat16* Yp = (const __nv_bfloat16*)dout;

    // Static Toeplitz table: entry tl (t = mOrig + tl): [Re 16B | Im 16B]
    // Re = [rh,rh,rl,rl, nh,nh,nl,nl], Im = [ih,ih,il,il, rh,rh,rl,rl]
    if (kStart == 0) {
        for (int tl = tid; tl < 1087; tl += 256) {
            int t = mOrig + tl;
            float zr, zi;
            if (t <= 1023) { int j = 1023 - t; zr = v_re[l * NN + j]; zi = -v_im[l * NN + j]; }
            else           { int j = t - 1023; zr = v_re[l * NN + j]; zi =  v_im[l * NN + j]; }
            u16 rh, rl, ih, il;
            split2u(zr, rh, rl);
            split2u(zi, ih, il);
            u16 nh = ih ^ 0x8000, nl = il ^ 0x8000;
            sts128(sb + TAB_OFF + tl * 32,      pk(rh, rh), pk(rl, rl), pk(nh, nh), pk(nl, nl));
            sts128(sb + TAB_OFF + tl * 32 + 16, pk(ih, ih), pk(il, il), pk(rh, rh), pk(rl, rl));
        }
    }

    const int ST = (1280 - kStart) / SK;

    // Per-thread A lane bases. Frag h rows: Rl = wm*32 + h*16 + (lane&15).
    const int Rl0 = wm * 32 + (lane & 15), Rl1 = Rl0 + 16;
    const int rl0 = Rl0 >> 1, rl1 = Rl1 >> 1;
    const int ty0 = Rl0 & 1,  ty1 = Rl1 & 1;
    const u32 khalf = (u32)(lane >> 4);
    const u32 tb0 = sb + TAB_OFF + (u32)(rl0 + 1023) * 32 + (u32)ty0 * 16 - khalf * 32;
    const u32 tb1 = sb + TAB_OFF + (u32)(rl1 + 1023) * 32 + (u32)ty1 * 16 - khalf * 32;
    const u32 wb0 = sb + W2A_OFF + (u32)rl0 * 1056 + (u32)ty0 * 16 + khalf * 32;
    const u32 wb1 = sb + W2A_OFF + (u32)rl1 * 1056 + (u32)ty1 * 16 + khalf * 32;
    const u32 bl = (u32)((lane & 15) * 128 + wn * 64 + (int)khalf * 16);
    const u32 sB0 = SWZ(bl);
    const u32 sB1 = SWZ(bl + 32);

    float4 acc[2][4];
#pragma unroll
    for (int i = 0; i < 2; i++)
#pragma unroll
        for (int j = 0; j < 4; j++) { acc[i][j].x = 0.f; acc[i][j].y = 0.f; acc[i][j].z = 0.f; acc[i][j].w = 0.f; }

    load_b(sb + B_OFF, kStart, tid, nBase, Bx, Yp);   // prologue stage 0

    u32 fA0[2][4], fA1[2][4], fB0[2][4], fB1[2][4];   // chunk pipeline (2 sets)

    for (int s = 0; s < ST; s++) {
        const int k0 = kStart + s * SK;
        const bool toep = (k0 < 1024);
        cp_wait<0>();
        __syncthreads();                                 // B(s) visible; warps past s-1
        if (s + 1 < ST)
            load_b(sb + B_OFF + ((s + 1) & 1) * B_STAGE, k0 + SK, tid, nBase, Bx, Yp);
        if (!toep) {
            build_w2(sb + W2A_OFF, k0, tid, l, mOrig, W2_re, W2_im);
            __syncthreads();                             // single-buffer W2A visible
        }

        const u32 bcur = sb + B_OFF + (s & 1) * B_STAGE;
        u32 a0base, a1base; int astep;
        if (toep) { a0base = tb0 - (u32)k0 * 32; a1base = tb1 - (u32)k0 * 32; astep = -64; }
        else      { a0base = wb0;                a1base = wb1;                astep =  64; }

        // chunk pipeline: 16 chunks (chunk = 2 orig k = 16 slots)
        {
            ldsm4(fA0[0][0], fA0[0][1], fA0[0][2], fA0[0][3], a0base);
            ldsm4(fA1[0][0], fA1[0][1], fA1[0][2], fA1[0][3], a1base);
            ldsm4t(fB0[0][0], fB0[0][1], fB0[0][2], fB0[0][3], bcur + sB0);
            ldsm4t(fB1[0][0], fB1[0][1], fB1[0][2], fB1[0][3], bcur + sB1);
        }
#pragma unroll
        for (int c = 0; c < 16; c++) {
            const int pc = c & 1, nc = pc ^ 1;
            if (c + 1 < 16) {
                const u32 aoff = (u32)((c + 1) * astep);
                const u32 boff = (u32)((c + 1) * 2048);
                ldsm4(fA0[nc][0], fA0[nc][1], fA0[nc][2], fA0[nc][3], a0base + aoff);
                ldsm4(fA1[nc][0], fA1[nc][1], fA1[nc][2], fA1[nc][3], a1base + aoff);
                ldsm4t(fB0[nc][0], fB0[nc][1], fB0[nc][2], fB0[nc][3], bcur + boff + sB0);
                ldsm4t(fB1[nc][0], fB1[nc][1], fB1[nc][2], fB1[nc][3], bcur + boff + sB1);
            }
            hmma(acc[0][0].x, acc[0][0].y, acc[0][0].z, acc[0][0].w,
                 fA0[pc][0], fA0[pc][1], fA0[pc][2], fA0[pc][3], fB0[pc][0], fB0[pc][1]);
            hmma(acc[0][1].x, acc[0][1].y, acc[0][1].z, acc[0][1].w,
                 fA0[pc][0], fA0[pc][1], fA0[pc][2], fA0[pc][3], fB0[pc][2], fB0[pc][3]);
            hmma(acc[0][2].x, acc[0][2].y, acc[0][2].z, acc[0][2].w,
                 fA0[pc][0], fA0[pc][1], fA0[pc][2], fA0[pc][3], fB1[pc][0], fB1[pc][1]);
            hmma(acc[0][3].x, acc[0][3].y, acc[0][3].z, acc[0][3].w,
                 fA0[pc][0], fA0[pc][1], fA0[pc][2], fA0[pc][3], fB1[pc][2], fB1[pc][3]);
            hmma(acc[1][0].x, acc[1][0].y, acc[1][0].z, acc[1][0].w,
                 fA1[pc][0], fA1[pc][1], fA1[pc][2], fA1[pc][3], fB0[pc][0], fB0[pc][1]);
            hmma(acc[1][1].x, acc[1][1].y, acc[1][1].z, acc[1][1].w,
                 fA1[pc][0], fA1[pc][1], fA1[pc][2], fA1[pc][3], fB0[pc][2], fB0[pc][3]);
            hmma(acc[1][2].x, acc[1][2].y, acc[1][2].z, acc[1][2].w,
                 fA1[pc][0], fA1[pc][1], fA1[pc][2], fA1[pc][3], fB1[pc][0], fB1[pc][1]);
            hmma(acc[1][3].x, acc[1][3].y, acc[1][3].z, acc[1][3].w,
                 fA1[pc][0], fA1[pc][1], fA1[pc][2], fA1[pc][3], fB1[pc][2], fB1[pc][3]);
        }
    }
    __syncthreads();   // all warps done before sC overwrites the table region

    // ---- epilogue: C -> SMEM (table region dead), threshold, emit planes ----
    float* sC = (float*)smem;   // [128][66] = 33792B <= 34816
#pragma unroll
    for (int im = 0; im < 2; im++)
#pragma unroll
        for (int jn = 0; jn < 4; jn++) {
            int r0 = wm * 32 + im * 16 + (lane >> 2);
            int c0 = wn * 32 + jn * 8 + (lane & 3) * 2;
            sC[r0 * 66 + c0]           = acc[im][jn].x;
            sC[r0 * 66 + c0 + 1]       = acc[im][jn].y;
            sC[(r0 + 8) * 66 + c0]     = acc[im][jn].z;
            sC[(r0 + 8) * 66 + c0 + 1] = acc[im][jn].w;
        }
    __syncthreads();

    const int cl = tid & 63;
    const int tr = tid >> 6;
    for (int t = tr; t < 64; t += 4) {
        float zr = sC[(2 * t) * 66 + cl];
        float zi = sC[(2 * t + 1) * 66 + cl];
        float mag = sqrtf(zr * zr + zi * zi);
        float sf = fmaxf(mag - BETA, 0.f) / fmaxf(mag, 1e-30f);
        float xr = zr * sf, xi = zi * sf;
        int R  = mOrig + t;
        int gc = nBase + cl;
        if (last) {
            ((float*)BxOut)[(size_t)R * BB + gc] = xr;   // fp32 Re(x); finalize copies out
        } else {
            u16 rh, rl, ih, il;
            split2u(xr, rh, rl);
            split2u(xi, ih, il);
            size_t o = (size_t)R * BB + gc;
            BxOut[o]                       = __ushort_as_bfloat16(rh);
            BxOut[o + (size_t)NN * BB]     = __ushort_as_bfloat16(rl);
            BxOut[o + (size_t)2 * NN * BB] = __ushort_as_bfloat16(ih);
            BxOut[o + (size_t)3 * NN * BB] = __ushort_as_bfloat16(il);
        }
    }
}

// ---------------- finalize: copy fp32 Re(x) from gBx[0] into d_out ----------------
__global__ void finalize(float* __restrict__ dst)
{
    const float* src = (const float*)gBx[0];     // layer 9 (cur=1) wrote gBx[0]
    long i = (long)blockIdx.x * 256 + threadIdx.x;
    if (i < (long)NN * BB) dst[i] = src[i];
}

extern "C" void kernel_launch(void* const* d_in, const int* in_sizes, int n_in,
                              void* d_out, int out_size)
{
    // Bind inputs by element count; first in size class = real part (confirmed R5).
    const float *v_re = 0, *v_im = 0, *W2_re = 0, *W2_im = 0, *y_re = 0, *y_im = 0;
    const long SV = (long)LL * NN, SW_ = (long)LL * NN * MM, SY = (long)MM * BB;
    for (int i = 0; i < n_in; i++) {
        const float* p = (const float*)d_in[i];
        long sz = in_sizes[i];
        if (sz == SV || sz == 4 * SV)        { if (!v_re)  v_re  = p; else v_im  = p; }
        else if (sz == SW_ || sz == 4 * SW_) { if (!W2_re) W2_re = p; else W2_im = p; }
        else if (sz == SY || sz == 4 * SY)   { if (!y_re)  y_re  = p; else y_im  = p; }
    }
    if (!v_re || !v_im || !W2_re || !W2_im || !y_re || !y_im) return;

    cudaFuncSetAttribute(gemm_layer, cudaFuncAttributeMaxDynamicSharedMemorySize, SMEM_TOTAL);

    makeBy<<<(MM * BB) / 256, 256>>>(y_re, y_im, (float*)d_out);

    dim3 grid(BB / 64, NN / 64);   // (8, 16) = 128 CTAs
    for (int l = 0; l < LL; l++) {
        int kStart = (l == 0) ? 1024 : 0;
        gemm_layer<<<grid, 256, SMEM_TOTAL>>>(l, kStart, l == LL - 1,
                                              v_re, v_im, W2_re, W2_im,
                                              (float*)d_out, l & 1);
    }
    finalize<<<(NN * BB) / 256, 256>>>((float*)d_out);
}

// round 15
// speedup vs baseline: 2.0147x; 1.0111x over previous
#include <cuda_runtime.h>
#include <cuda_bf16.h>

#define NN 1024
#define MM 256
#define BB 512
#define LL 10
#define BETA 0.01f

#define SK 16                 // orig k per stage
#define TAB_OFF 0             // 1055 entries x 32B = 33760 (pad 33792)
#define W2A_OFF 33792         // 32 rows x 544B = 17408
#define B_OFF   51200         // 3-deep ring x 16384 (128 slot-rows x 128B)
#define B_STAGE 16384
#define SMEM_TOTAL 100352     // <= 113KB -> 2 CTAs/SM

typedef unsigned u32;
typedef unsigned short u16;

// ONLY global scratch: x planes [rh, rl, ih, il], ping-pong. 8MB total (proven budget).
__device__ __nv_bfloat16 gBx[2][(size_t)4 * NN * BB];

// ---------------- helpers ----------------
__device__ __forceinline__ u32 s2u(const void* p) {
    u32 a;
    asm("{ .reg .u64 t; cvta.to.shared.u64 t, %1; cvt.u32.u64 %0, t; }" : "=r"(a) : "l"(p));
    return a;
}
#define SWZ(o) ((o) ^ (((o) >> 3) & 0x70))

__device__ __forceinline__ void cpa16(u32 dst, const void* src) {
    asm volatile("cp.async.cg.shared.global [%0], [%1], 16;" :: "r"(dst), "l"(src));
}
__device__ __forceinline__ void cp_commit() {
    asm volatile("cp.async.commit_group;" ::: "memory");
}
template <int N_> __device__ __forceinline__ void cp_wait() {
    asm volatile("cp.async.wait_group %0;" :: "n"(N_) : "memory");
}
__device__ __forceinline__ void sts128(u32 a, u32 x, u32 y, u32 z, u32 w) {
    asm volatile("st.shared.v4.b32 [%0], {%1,%2,%3,%4};"
                 :: "r"(a), "r"(x), "r"(y), "r"(z), "r"(w) : "memory");
}
__device__ __forceinline__ void ldsm4(u32& r0, u32& r1, u32& r2, u32& r3, u32 a) {
    asm volatile("ldmatrix.sync.aligned.m8n8.x4.shared.b16 {%0,%1,%2,%3}, [%4];"
                 : "=r"(r0), "=r"(r1), "=r"(r2), "=r"(r3) : "r"(a));
}
__device__ __forceinline__ void ldsm4t(u32& r0, u32& r1, u32& r2, u32& r3, u32 a) {
    asm volatile("ldmatrix.sync.aligned.m8n8.x4.trans.shared.b16 {%0,%1,%2,%3}, [%4];"
                 : "=r"(r0), "=r"(r1), "=r"(r2), "=r"(r3) : "r"(a));
}
__device__ __forceinline__ void hmma(float& d0, float& d1, float& d2, float& d3,
                                     u32 a0, u32 a1, u32 a2, u32 a3, u32 b0, u32 b1) {
    asm volatile("mma.sync.aligned.m16n8k16.row.col.f32.bf16.bf16.f32 "
                 "{%0,%1,%2,%3}, {%4,%5,%6,%7}, {%8,%9}, {%0,%1,%2,%3};"
                 : "+f"(d0), "+f"(d1), "+f"(d2), "+f"(d3)
                 : "r"(a0), "r"(a1), "r"(a2), "r"(a3), "r"(b0), "r"(b1));
}
__device__ __forceinline__ void split2u(float v, u16& h, u16& lo) {
    __nv_bfloat16 hb = __float2bfloat16(v);
    h = __bfloat16_as_ushort(hb);
    lo = __bfloat16_as_ushort(__float2bfloat16(v - __bfloat162float(hb)));
}
__device__ __forceinline__ u32 pk(u16 lo, u16 hi) { return (u32)lo | ((u32)hi << 16); }

// ---------------- pre-kernel: y planes [rh, rl, ih, il] into d_out scratch ----------------
__global__ void makeBy(const float* __restrict__ y_re, const float* __restrict__ y_im,
                       float* __restrict__ dout)
{
    int e = blockIdx.x * 256 + threadIdx.x;    // over MM*BB
    int n = e & 511;
    int m = e >> 9;
    u16 rh, rl, ih, il;
    split2u(y_re[(size_t)m * BB + n], rh, rl);
    split2u(y_im[(size_t)m * BB + n], ih, il);
    __nv_bfloat16* yp = (__nv_bfloat16*)dout;
    size_t o = (size_t)m * BB + n;
    yp[o]                       = __ushort_as_bfloat16(rh);
    yp[o + (size_t)MM * BB]     = __ushort_as_bfloat16(rl);
    yp[o + (size_t)2 * MM * BB] = __ushort_as_bfloat16(ih);
    yp[o + (size_t)3 * MM * BB] = __ushort_as_bfloat16(il);
}

// ---------------- B stage: 16 k x 8 slot-rows x 128B via cp.async (128 threads) ----------------
// slot j -> plane [xrh,xrl,xrh,xrl, xih,xil,xih,xil] = (j&1) + ((j>>2)<<1)
__device__ __forceinline__ void load_b(u32 bstage, int k0, int tid, int nBase,
                                       const __nv_bfloat16* __restrict__ Bx,
                                       const __nv_bfloat16* __restrict__ Yp)
{
#pragma unroll
    for (int rep = 0; rep < 8; rep++) {
        int idx = tid + rep * 128;
        int row = idx >> 3, seg = idx & 7;
        int k = k0 + (row >> 3);
        int j = row & 7;
        int p = (j & 1) + ((j >> 2) << 1);
        const __nv_bfloat16* src = (k < 1024)
            ? (Bx + ((size_t)p * NN + k) * BB + nBase + seg * 8)
            : (Yp + ((size_t)p * MM + (k - 1024)) * BB + nBase + seg * 8);
        cpa16(bstage + SWZ((u32)(row * 128 + seg * 16)), src);
    }
    cp_commit();
}

// ---------------- W2 A stage (single buffer): 32 rows x 16 k, 32B entries, 544B stride ----
__device__ __forceinline__ void build_w2(u32 w2base, int k0, int tid, int l, int mOrig,
                                         const float* __restrict__ W2_re,
                                         const float* __restrict__ W2_im)
{
#pragma unroll
    for (int rep = 0; rep < 4; rep++) {
        int q = tid + rep * 128;
        int rl = q >> 4, dk = q & 15;
        int kg = k0 + dk - 1024;
        size_t g = ((size_t)l * NN + mOrig + rl) * MM + kg;
        float zr = W2_re[g], zi = W2_im[g];
        u16 rh, rl2, ih, il;
        split2u(zr, rh, rl2);
        split2u(zi, ih, il);
        u16 nh = ih ^ 0x8000, nl = il ^ 0x8000;
        u32 base = w2base + (u32)rl * 544 + (u32)dk * 32;
        sts128(base,      pk(rh, rh), pk(rl2, rl2), pk(nh, nh), pk(nl, nl));
        sts128(base + 16, pk(ih, ih), pk(il, il),   pk(rh, rh), pk(rl2, rl2));
    }
}

// ---------------- fused layer ----------------
__global__ __launch_bounds__(128, 2)
void gemm_layer(int l, int kStart, int last,
                const float* __restrict__ v_re, const float* __restrict__ v_im,
                const float* __restrict__ W2_re, const float* __restrict__ W2_im,
                float* __restrict__ dout, int cur)
{
    extern __shared__ __align__(16) char smem[];
    const u32 sb = s2u(smem);
    const int tid = threadIdx.x, wid = tid >> 5, lane = tid & 31;
    const int wm = wid & 1, wn = wid >> 1;     // warps 2x2, warp tile 32(M')x32(N)
    const int mOrig = blockIdx.y * 32;         // 32 orig rows per CTA (M' = 64)
    const int nBase = blockIdx.x * 64;
    const __nv_bfloat16* Bx = gBx[cur];
    __nv_bfloat16* BxOut = gBx[cur ^ 1];
    const __nv_bfloat16* Yp = (const __nv_bfloat16*)dout;

    // Static Toeplitz table: entry tl (t = mOrig + tl), 1055 entries: [Re 16B | Im 16B]
    // Re = [rh,rh,rl,rl, nh,nh,nl,nl], Im = [ih,ih,il,il, rh,rh,rl,rl]
    if (kStart == 0) {
        for (int tl = tid; tl < 1055; tl += 128) {
            int t = mOrig + tl;
            float zr, zi;
            if (t <= 1023) { int j = 1023 - t; zr = v_re[l * NN + j]; zi = -v_im[l * NN + j]; }
            else           { int j = t - 1023; zr = v_re[l * NN + j]; zi =  v_im[l * NN + j]; }
            u16 rh, rl, ih, il;
            split2u(zr, rh, rl);
            split2u(zi, ih, il);
            u16 nh = ih ^ 0x8000, nl = il ^ 0x8000;
            sts128(sb + TAB_OFF + tl * 32,      pk(rh, rh), pk(rl, rl), pk(nh, nh), pk(nl, nl));
            sts128(sb + TAB_OFF + tl * 32 + 16, pk(ih, ih), pk(il, il), pk(rh, rh), pk(rl, rl));
        }
    }

    const int ST = (1280 - kStart) / SK;

    // Per-thread A lane bases. Frag h rows: Rl = wm*32 + h*16 + (lane&15).
    const int Rl0 = wm * 32 + (lane & 15), Rl1 = Rl0 + 16;
    const int rl0 = Rl0 >> 1, rl1 = Rl1 >> 1;
    const int ty0 = Rl0 & 1,  ty1 = Rl1 & 1;
    const u32 khalf = (u32)(lane >> 4);
    const u32 tb0 = sb + TAB_OFF + (u32)(rl0 + 1023) * 32 + (u32)ty0 * 16 - khalf * 32;
    const u32 tb1 = sb + TAB_OFF + (u32)(rl1 + 1023) * 32 + (u32)ty1 * 16 - khalf * 32;
    const u32 wb0 = sb + W2A_OFF + (u32)rl0 * 544 + (u32)ty0 * 16 + khalf * 32;
    const u32 wb1 = sb + W2A_OFF + (u32)rl1 * 544 + (u32)ty1 * 16 + khalf * 32;
    const u32 bl = (u32)((lane & 15) * 128 + wn * 64 + (int)khalf * 16);
    const u32 sB0 = SWZ(bl);
    const u32 sB1 = SWZ(bl + 32);

    float4 acc[2][4];
#pragma unroll
    for (int i = 0; i < 2; i++)
#pragma unroll
        for (int j = 0; j < 4; j++) { acc[i][j].x = 0.f; acc[i][j].y = 0.f; acc[i][j].z = 0.f; acc[i][j].w = 0.f; }

    // Prologue: 2 stages in flight (3-deep ring, wait<1>)
    load_b(sb + B_OFF + 0 * B_STAGE, kStart + 0 * SK, tid, nBase, Bx, Yp);
    load_b(sb + B_OFF + 1 * B_STAGE, kStart + 1 * SK, tid, nBase, Bx, Yp);

    u32 fA0[2][4], fA1[2][4], fB0[2][4], fB1[2][4];   // chunk pipeline (2 sets)
    int bi = 0, li = 2;

    for (int s = 0; s < ST; s++) {
        const int k0 = kStart + s * SK;
        const bool toep = (k0 < 1024);
        cp_wait<1>();            // stage-s group complete (s+1 may be in flight)
        __syncthreads();         // B(s) visible; all warps past stage s-1
        if (s + 2 < ST) load_b(sb + B_OFF + li * B_STAGE, k0 + 2 * SK, tid, nBase, Bx, Yp);
        else            cp_commit();   // dummy: keep group arithmetic uniform
        li = (li == 2) ? 0 : li + 1;
        if (!toep) {
            build_w2(sb + W2A_OFF, k0, tid, l, mOrig, W2_re, W2_im);
            __syncthreads();     // single-buffer W2A visible
        }

        const u32 bcur = sb + B_OFF + bi * B_STAGE;
        bi = (bi == 2) ? 0 : bi + 1;
        u32 a0base, a1base; int astep;
        if (toep) { a0base = tb0 - (u32)k0 * 32; a1base = tb1 - (u32)k0 * 32; astep = -64; }
        else      { a0base = wb0;                a1base = wb1;                astep =  64; }

        // chunk pipeline: 8 chunks (chunk = 2 orig k = 16 slots)
        {
            ldsm4(fA0[0][0], fA0[0][1], fA0[0][2], fA0[0][3], a0base);
            ldsm4(fA1[0][0], fA1[0][1], fA1[0][2], fA1[0][3], a1base);
            ldsm4t(fB0[0][0], fB0[0][1], fB0[0][2], fB0[0][3], bcur + sB0);
            ldsm4t(fB1[0][0], fB1[0][1], fB1[0][2], fB1[0][3], bcur + sB1);
        }
#pragma unroll
        for (int c = 0; c < 8; c++) {
            const int pc = c & 1, nc = pc ^ 1;
            if (c + 1 < 8) {
                const u32 aoff = (u32)((c + 1) * astep);
                const u32 boff = (u32)((c + 1) * 2048);
                ldsm4(fA0[nc][0], fA0[nc][1], fA0[nc][2], fA0[nc][3], a0base + aoff);
                ldsm4(fA1[nc][0], fA1[nc][1], fA1[nc][2], fA1[nc][3], a1base + aoff);
                ldsm4t(fB0[nc][0], fB0[nc][1], fB0[nc][2], fB0[nc][3], bcur + boff + sB0);
                ldsm4t(fB1[nc][0], fB1[nc][1], fB1[nc][2], fB1[nc][3], bcur + boff + sB1);
            }
            hmma(acc[0][0].x, acc[0][0].y, acc[0][0].z, acc[0][0].w,
                 fA0[pc][0], fA0[pc][1], fA0[pc][2], fA0[pc][3], fB0[pc][0], fB0[pc][1]);
            hmma(acc[0][1].x, acc[0][1].y, acc[0][1].z, acc[0][1].w,
                 fA0[pc][0], fA0[pc][1], fA0[pc][2], fA0[pc][3], fB0[pc][2], fB0[pc][3]);
            hmma(acc[0][2].x, acc[0][2].y, acc[0][2].z, acc[0][2].w,
                 fA0[pc][0], fA0[pc][1], fA0[pc][2], fA0[pc][3], fB1[pc][0], fB1[pc][1]);
            hmma(acc[0][3].x, acc[0][3].y, acc[0][3].z, acc[0][3].w,
                 fA0[pc][0], fA0[pc][1], fA0[pc][2], fA0[pc][3], fB1[pc][2], fB1[pc][3]);
            hmma(acc[1][0].x, acc[1][0].y, acc[1][0].z, acc[1][0].w,
                 fA1[pc][0], fA1[pc][1], fA1[pc][2], fA1[pc][3], fB0[pc][0], fB0[pc][1]);
            hmma(acc[1][1].x, acc[1][1].y, acc[1][1].z, acc[1][1].w,
                 fA1[pc][0], fA1[pc][1], fA1[pc][2], fA1[pc][3], fB0[pc][2], fB0[pc][3]);
            hmma(acc[1][2].x, acc[1][2].y, acc[1][2].z, acc[1][2].w,
                 fA1[pc][0], fA1[pc][1], fA1[pc][2], fA1[pc][3], fB1[pc][0], fB1[pc][1]);
            hmma(acc[1][3].x, acc[1][3].y, acc[1][3].z, acc[1][3].w,
                 fA1[pc][0], fA1[pc][1], fA1[pc][2], fA1[pc][3], fB1[pc][2], fB1[pc][3]);
        }
    }
    __syncthreads();   // all warps done before sC overwrites the table region

    // ---- epilogue: C -> SMEM (table region dead), threshold, emit planes ----
    float* sC = (float*)smem;   // [64][66] = 16896B <= 33792
#pragma unroll
    for (int im = 0; im < 2; im++)
#pragma unroll
        for (int jn = 0; jn < 4; jn++) {
            int r0 = wm * 32 + im * 16 + (lane >> 2);
            int c0 = wn * 32 + jn * 8 + (lane & 3) * 2;
            sC[r0 * 66 + c0]           = acc[im][jn].x;
            sC[r0 * 66 + c0 + 1]       = acc[im][jn].y;
            sC[(r0 + 8) * 66 + c0]     = acc[im][jn].z;
            sC[(r0 + 8) * 66 + c0 + 1] = acc[im][jn].w;
        }
    __syncthreads();

    const int cl = tid & 63;
    const int tr = tid >> 6;           // 0..1
    for (int t = tr; t < 32; t += 2) {
        float zr = sC[(2 * t) * 66 + cl];
        float zi = sC[(2 * t + 1) * 66 + cl];
        float mag = sqrtf(zr * zr + zi * zi);
        float sf = fmaxf(mag - BETA, 0.f) / fmaxf(mag, 1e-30f);
        float xr = zr * sf, xi = zi * sf;
        int R  = mOrig + t;
        int gc = nBase + cl;
        if (last) {
            ((float*)BxOut)[(size_t)R * BB + gc] = xr;   // fp32 Re(x); finalize copies out
        } else {
            u16 rh, rl, ih, il;
            split2u(xr, rh, rl);
            split2u(xi, ih, il);
            size_t o = (size_t)R * BB + gc;
            BxOut[o]                       = __ushort_as_bfloat16(rh);
            BxOut[o + (size_t)NN * BB]     = __ushort_as_bfloat16(rl);
            BxOut[o + (size_t)2 * NN * BB] = __ushort_as_bfloat16(ih);
            BxOut[o + (size_t)3 * NN * BB] = __ushort_as_bfloat16(il);
        }
    }
}

// ---------------- finalize: copy fp32 Re(x) from gBx[0] into d_out ----------------
__global__ void finalize(float* __restrict__ dst)
{
    const float* src = (const float*)gBx[0];     // layer 9 (cur=1) wrote gBx[0]
    long i = (long)blockIdx.x * 256 + threadIdx.x;
    if (i < (long)NN * BB) dst[i] = src[i];
}

extern "C" void kernel_launch(void* const* d_in, const int* in_sizes, int n_in,
                              void* d_out, int out_size)
{
    // Bind inputs by element count; first in size class = real part (confirmed R5).
    const float *v_re = 0, *v_im = 0, *W2_re = 0, *W2_im = 0, *y_re = 0, *y_im = 0;
    const long SV = (long)LL * NN, SW_ = (long)LL * NN * MM, SY = (long)MM * BB;
    for (int i = 0; i < n_in; i++) {
        const float* p = (const float*)d_in[i];
        long sz = in_sizes[i];
        if (sz == SV || sz == 4 * SV)        { if (!v_re)  v_re  = p; else v_im  = p; }
        else if (sz == SW_ || sz == 4 * SW_) { if (!W2_re) W2_re = p; else W2_im = p; }
        else if (sz == SY || sz == 4 * SY)   { if (!y_re)  y_re  = p; else y_im  = p; }
    }
    if (!v_re || !v_im || !W2_re || !W2_im || !y_re || !y_im) return;

    cudaFuncSetAttribute(gemm_layer, cudaFuncAttributeMaxDynamicSharedMemorySize, SMEM_TOTAL);

    makeBy<<<(MM * BB) / 256, 256>>>(y_re, y_im, (float*)d_out);

    dim3 grid(BB / 64, NN / 32);   // (8, 32) = 256 CTAs
    for (int l = 0; l < LL; l++) {
        int kStart = (l == 0) ? 1024 : 0;
        gemm_layer<<<grid, 128, SMEM_TOTAL>>>(l, kStart, l == LL - 1,
                                              v_re, v_im, W2_re, W2_im,
                                              (float*)d_out, l & 1);
    }
    finalize<<<(NN * BB) / 256, 256>>>((float*)d_out);
}